// round 1
// baseline (speedup 1.0000x reference)
#include <cuda_runtime.h>
#include <math.h>

#define Bb 8
#define Nn 2048
#define Cc 1024
#define Hh 16
#define Dd 64
#define Mm (Bb*Nn)      /* 16384 */
#define C3 (3*Cc)       /* 3072  */
#define KK 5
#define RCH 64

// ---- scratch (static device globals; no allocations allowed) ----
__device__ float g_qkv[(size_t)Mm*C3];     // 192 MB: q|k|v per row
__device__ float g_odwc[(size_t)Mm*Cc];    // 64 MB: o + dwc
__device__ float g_kv[Bb*Hh*Dd*Dd];        // per-(b,h) K^T V
__device__ float g_ksum[Bb*Hh*Dd];
__device__ float g_bn_a[Cc], g_bn_b[Cc], g_scale[Cc];
__device__ float g_psum[RCH*Cc], g_psq[RCH*Cc];

// ---------------------------------------------------------------------------
// K1: per-channel partial sums over row chunks (deterministic, no atomics)
// ---------------------------------------------------------------------------
__global__ void bn_partial(const float* __restrict__ x) {
    int c = blockIdx.x * 128 + threadIdx.x;
    int chunk = blockIdx.y;
    const int RPC = Mm / RCH;                 // 256 rows per chunk
    const float* p = x + (size_t)(chunk * RPC) * Cc + c;
    float s = 0.f, sq = 0.f;
    for (int r = 0; r < RPC; r++) {
        float v = p[(size_t)r * Cc];
        s += v; sq += v * v;
    }
    g_psum[chunk * Cc + c] = s;
    g_psq[chunk * Cc + c]  = sq;
}

// ---------------------------------------------------------------------------
// K2: finalize BN affine + softplus(scale_p)
// ---------------------------------------------------------------------------
__global__ void bn_finalize(const float* __restrict__ gamma,
                            const float* __restrict__ beta,
                            const float* __restrict__ scale_p) {
    int c = blockIdx.x * 256 + threadIdx.x;
    float s = 0.f, sq = 0.f;
    for (int i = 0; i < RCH; i++) { s += g_psum[i * Cc + c]; sq += g_psq[i * Cc + c]; }
    float mean = s / (float)Mm;
    float var  = sq / (float)Mm - mean * mean;     // biased, matches torch BN
    float rstd = rsqrtf(var + 1e-5f);
    float a = rstd * gamma[c];
    g_bn_a[c] = a;
    g_bn_b[c] = beta[c] - mean * a;
    float sp = scale_p[c];
    g_scale[c] = (sp > 20.f) ? sp : log1pf(expf(sp));
}

// ---------------------------------------------------------------------------
// K3/K7: tiled fp32 SGEMM  C[M,N] = A[M,K] @ B[K,N] + bias
// BM=BN=128, BK=16, 256 threads, 8x8 per thread. Optional fused BN on A-load.
// ---------------------------------------------------------------------------
template <int FUSE_BN>
__global__ __launch_bounds__(256) void sgemm(const float* __restrict__ A,
                                             const float* __restrict__ Bm,
                                             const float* __restrict__ bias,
                                             float* __restrict__ Cout,
                                             int Kdim, int Ndim) {
    __shared__ float As[16][132];   // [k][m], padded (132*4 = 16B-aligned rows)
    __shared__ float Bs[16][128];   // [k][n]

    int t  = threadIdx.x;
    int m0 = blockIdx.y * 128, n0 = blockIdx.x * 128;
    int ty = t >> 4, tx = t & 15;

    int arow = t >> 1, aseg = (t & 1) * 8;   // A: 2 threads per row, 8 floats each
    int brow = t >> 4, bcol = (t & 15) * 8;  // B: 16 threads per row

    float acc[8][8];
#pragma unroll
    for (int i = 0; i < 8; i++)
#pragma unroll
        for (int j = 0; j < 8; j++) acc[i][j] = 0.f;

    for (int k0 = 0; k0 < Kdim; k0 += 16) {
        // --- load A tile (optionally BN-normalized) ---
        const float* ap = A + (size_t)(m0 + arow) * Kdim + k0 + aseg;
        float4 a0 = *(const float4*)ap;
        float4 a1 = *(const float4*)(ap + 4);
        float av[8] = {a0.x, a0.y, a0.z, a0.w, a1.x, a1.y, a1.z, a1.w};
        if (FUSE_BN) {
#pragma unroll
            for (int i = 0; i < 8; i++) {
                int kc = k0 + aseg + i;
                av[i] = av[i] * g_bn_a[kc] + g_bn_b[kc];
            }
        }
#pragma unroll
        for (int i = 0; i < 8; i++) As[aseg + i][arow] = av[i];

        // --- load B tile ---
        const float* bp = Bm + (size_t)(k0 + brow) * Ndim + n0 + bcol;
        *(float4*)&Bs[brow][bcol]     = *(const float4*)bp;
        *(float4*)&Bs[brow][bcol + 4] = *(const float4*)(bp + 4);

        __syncthreads();

#pragma unroll
        for (int kk = 0; kk < 16; kk++) {
            float4 ra0 = *(const float4*)&As[kk][ty * 8];
            float4 ra1 = *(const float4*)&As[kk][ty * 8 + 4];
            float4 rb0 = *(const float4*)&Bs[kk][tx * 8];
            float4 rb1 = *(const float4*)&Bs[kk][tx * 8 + 4];
            float ra[8] = {ra0.x, ra0.y, ra0.z, ra0.w, ra1.x, ra1.y, ra1.z, ra1.w};
            float rb[8] = {rb0.x, rb0.y, rb0.z, rb0.w, rb1.x, rb1.y, rb1.z, rb1.w};
#pragma unroll
            for (int i = 0; i < 8; i++)
#pragma unroll
                for (int j = 0; j < 8; j++) acc[i][j] += ra[i] * rb[j];
        }
        __syncthreads();
    }

    // --- epilogue: add bias, store ---
    float4 bv0 = *(const float4*)&bias[n0 + tx * 8];
    float4 bv1 = *(const float4*)&bias[n0 + tx * 8 + 4];
    float bb[8] = {bv0.x, bv0.y, bv0.z, bv0.w, bv1.x, bv1.y, bv1.z, bv1.w};
#pragma unroll
    for (int i = 0; i < 8; i++) {
        float* cp = Cout + (size_t)(m0 + ty * 8 + i) * Ndim + n0 + tx * 8;
        float4 o0 = {acc[i][0] + bb[0], acc[i][1] + bb[1], acc[i][2] + bb[2], acc[i][3] + bb[3]};
        float4 o1 = {acc[i][4] + bb[4], acc[i][5] + bb[5], acc[i][6] + bb[6], acc[i][7] + bb[7]};
        *(float4*)cp       = o0;
        *(float4*)(cp + 4) = o1;
    }
}

// ---------------------------------------------------------------------------
// K4: focused feature map, in place on q / k rows (norm over full C=1024)
// ---------------------------------------------------------------------------
__global__ void focus_kernel() {
    int bx  = blockIdx.x;
    int m   = bx >> 1;
    int sel = bx & 1;                              // 0 = q, 1 = k
    float* p = g_qkv + (size_t)m * C3 + sel * Cc;
    int t = threadIdx.x;                           // 256 threads, 4 elems each

    float t3[4];
    float s2 = 0.f, s6 = 0.f;
#pragma unroll
    for (int i = 0; i < 4; i++) {
        int c = t + i * 256;
        float v = fmaxf(p[c], 0.f) + 1e-6f;
        v = v / g_scale[c];
        s2 += v * v;
        float v3 = v * v * v;
        t3[i] = v3;
        s6 += v3 * v3;
    }
    // block reduction of (s2, s6)
    __shared__ float sh2[8], sh6[8];
#pragma unroll
    for (int off = 16; off; off >>= 1) {
        s2 += __shfl_xor_sync(0xffffffffu, s2, off);
        s6 += __shfl_xor_sync(0xffffffffu, s6, off);
    }
    int w = t >> 5, lane = t & 31;
    if (lane == 0) { sh2[w] = s2; sh6[w] = s6; }
    __syncthreads();
    if (t == 0) {
        float a = 0.f, b = 0.f;
        for (int i = 0; i < 8; i++) { a += sh2[i]; b += sh6[i]; }
        sh2[0] = a; sh6[0] = b;
    }
    __syncthreads();
    float factor = sqrtf(sh2[0] / sh6[0]);         // ||t|| / ||t^3||
#pragma unroll
    for (int i = 0; i < 4; i++) p[t + i * 256] = t3[i] * factor;
}

// ---------------------------------------------------------------------------
// K5: per (b,h): kv[d][e] = sum_n k[n,d] v[n,e]; ksum[d] = sum_n k[n,d]
// ---------------------------------------------------------------------------
__global__ __launch_bounds__(256) void kv_kernel() {
    int bh = blockIdx.x;
    int b = bh >> 4, h = bh & 15;
    const float* kbase = g_qkv + (size_t)(b * Nn) * C3 + Cc + h * Dd;
    const float* vbase = kbase + Cc;

    __shared__ float ks[32][65], vs[32][65];
    int t = threadIdx.x;
    int dr = (t >> 4) << 2, ec = (t & 15) << 2;

    float acc[4][4];
#pragma unroll
    for (int i = 0; i < 4; i++)
#pragma unroll
        for (int j = 0; j < 4; j++) acc[i][j] = 0.f;
    float ksacc = 0.f;

    for (int n0 = 0; n0 < Nn; n0 += 32) {
        __syncthreads();
#pragma unroll
        for (int i = 0; i < 8; i++) {
            int idx = t + i * 256;
            int r = idx >> 6, c = idx & 63;
            ks[r][c] = kbase[(size_t)(n0 + r) * C3 + c];
            vs[r][c] = vbase[(size_t)(n0 + r) * C3 + c];
        }
        __syncthreads();
#pragma unroll 8
        for (int n = 0; n < 32; n++) {
            float kd0 = ks[n][dr], kd1 = ks[n][dr + 1], kd2 = ks[n][dr + 2], kd3 = ks[n][dr + 3];
            float v0 = vs[n][ec], v1 = vs[n][ec + 1], v2 = vs[n][ec + 2], v3 = vs[n][ec + 3];
            acc[0][0] += kd0 * v0; acc[0][1] += kd0 * v1; acc[0][2] += kd0 * v2; acc[0][3] += kd0 * v3;
            acc[1][0] += kd1 * v0; acc[1][1] += kd1 * v1; acc[1][2] += kd1 * v2; acc[1][3] += kd1 * v3;
            acc[2][0] += kd2 * v0; acc[2][1] += kd2 * v1; acc[2][2] += kd2 * v2; acc[2][3] += kd2 * v3;
            acc[3][0] += kd3 * v0; acc[3][1] += kd3 * v1; acc[3][2] += kd3 * v2; acc[3][3] += kd3 * v3;
        }
        if (t < 64) {
#pragma unroll 8
            for (int n = 0; n < 32; n++) ksacc += ks[n][t];
        }
    }

    float* kvout = g_kv + bh * (Dd * Dd);
#pragma unroll
    for (int i = 0; i < 4; i++)
#pragma unroll
        for (int j = 0; j < 4; j++)
            kvout[(dr + i) * Dd + ec + j] = acc[i][j];
    if (t < 64) g_ksum[bh * Dd + t] = ksacc;
}

// ---------------------------------------------------------------------------
// K6: o[n,e] = z * sum_d q[n,d] kv[d,e]   fused with depthwise-conv residual
// ---------------------------------------------------------------------------
__global__ __launch_bounds__(256) void o_dwc_kernel(const float* __restrict__ dwc_w,
                                                    const float* __restrict__ dwc_b) {
    int bh = blockIdx.x;
    int b = bh >> 4, h = bh & 15;
    int n0 = blockIdx.y * 128;

    __shared__ float kvs[64][65];
    __shared__ float ksums[64];
    __shared__ float qrow[8][64];

    int t = threadIdx.x;
    int w = t >> 5, lane = t & 31;

#pragma unroll
    for (int i = 0; i < 16; i++) {
        int idx = t + i * 256;
        kvs[idx >> 6][idx & 63] = g_kv[bh * (Dd * Dd) + idx];
    }
    if (t < 64) ksums[t] = g_ksum[bh * Dd + t];
    __syncthreads();

    const float* qbase = g_qkv + (size_t)(b * Nn) * C3 + h * Dd;
    const float* vbase = g_qkv + (size_t)(b * Nn) * C3 + 2 * Cc + h * Dd;

    // per-channel dwc weights for this warp's two channels
    int c0 = h * 64 + lane, c1 = h * 64 + lane + 32;
    float w0[5], w1[5];
#pragma unroll
    for (int j = 0; j < 5; j++) { w0[j] = dwc_w[c0 * 5 + j]; w1[j] = dwc_w[c1 * 5 + j]; }
    float db0 = dwc_b[c0], db1 = dwc_b[c1];

    for (int r = w; r < 128; r += 8) {
        int n = n0 + r;
        const float* qp = qbase + (size_t)n * C3;
        qrow[w][lane]      = qp[lane];
        qrow[w][lane + 32] = qp[lane + 32];
        __syncwarp();

        float s = qrow[w][lane] * ksums[lane] + qrow[w][lane + 32] * ksums[lane + 32];
#pragma unroll
        for (int off = 16; off; off >>= 1) s += __shfl_xor_sync(0xffffffffu, s, off);
        float z = 1.f / (s + 1e-6f);

        float acc0 = 0.f, acc1 = 0.f;
#pragma unroll
        for (int d = 0; d < 64; d++) {
            float qd = qrow[w][d];
            acc0 += qd * kvs[d][lane];
            acc1 += qd * kvs[d][lane + 32];
        }

        float dw0 = db0, dw1 = db1;
#pragma unroll
        for (int j = 0; j < 5; j++) {
            int nn = n + j - 2;
            if ((unsigned)nn < (unsigned)Nn) {
                const float* vp = vbase + (size_t)nn * C3;
                dw0 += vp[lane]      * w0[j];
                dw1 += vp[lane + 32] * w1[j];
            }
        }

        float* op = g_odwc + (size_t)(b * Nn + n) * Cc + h * 64;
        op[lane]      = acc0 * z + dw0;
        op[lane + 32] = acc1 * z + dw1;
        __syncwarp();
    }
}

// ---------------------------------------------------------------------------
extern "C" void kernel_launch(void* const* d_in, const int* in_sizes, int n_in,
                              void* d_out, int out_size) {
    const float* x       = (const float*)d_in[0];
    const float* gamma   = (const float*)d_in[1];
    const float* beta    = (const float*)d_in[2];
    const float* Wqkv    = (const float*)d_in[3];
    const float* bqkv    = (const float*)d_in[4];
    const float* scale_p = (const float*)d_in[5];
    const float* dwc_w   = (const float*)d_in[6];
    const float* dwc_b   = (const float*)d_in[7];
    const float* Wproj   = (const float*)d_in[8];
    const float* bproj   = (const float*)d_in[9];
    float* out = (float*)d_out;

    void *p_qkv, *p_odwc;
    cudaGetSymbolAddress(&p_qkv, g_qkv);
    cudaGetSymbolAddress(&p_odwc, g_odwc);
    float* qkv  = (float*)p_qkv;
    float* odwc = (float*)p_odwc;

    // 1. BN stats
    bn_partial<<<dim3(8, RCH), 128>>>(x);
    bn_finalize<<<4, 256>>>(gamma, beta, scale_p);

    // 2. QKV GEMM with fused BN on A-load: [16384,1024] @ [1024,3072]
    sgemm<1><<<dim3(C3 / 128, Mm / 128), 256>>>(x, Wqkv, bqkv, qkv, Cc, C3);

    // 3. focus(q), focus(k) in place
    focus_kernel<<<2 * Mm, 256>>>();

    // 4. per-(b,h) K^T V and k-sum
    kv_kernel<<<Bb * Hh, 256>>>();

    // 5. o = (q @ kv) * z, fused with depthwise conv residual
    o_dwc_kernel<<<dim3(Bb * Hh, Nn / 128), 256>>>(dwc_w, dwc_b);

    // 6. proj GEMM: [16384,1024] @ [1024,1024] + bias -> out
    sgemm<0><<<dim3(Cc / 128, Mm / 128), 256>>>(odwc, Wproj, bproj, out, Cc, Cc);
}

// round 3
// speedup vs baseline: 1.9614x; 1.9614x over previous
#include <cuda_runtime.h>
#include <cuda_bf16.h>
#include <math.h>
#include <stdint.h>

#define Bb 8
#define Nn 2048
#define Cc 1024
#define Hh 16
#define Dd 64
#define Mm (Bb*Nn)      /* 16384 */
#define C3 (3*Cc)       /* 3072  */
#define RCH 64

// ---- scratch (static device globals; no allocations allowed) ----
__device__ float g_qkv[(size_t)Mm*C3];     // q|k|v per row (f32)
__device__ float g_kv[Bb*Hh*Dd*Dd];
__device__ float g_ksum[Bb*Hh*Dd];
__device__ float g_bn_a[Cc], g_bn_b[Cc], g_scale[Cc];
__device__ float g_psum[RCH*Cc], g_psq[RCH*Cc];
// bf16 hi/lo split operands for tensor-core GEMMs
__device__ __nv_bfloat16 g_Ahi[(size_t)Mm*Cc], g_Alo[(size_t)Mm*Cc];
__device__ __nv_bfloat16 g_Ohi[(size_t)Mm*Cc], g_Olo[(size_t)Mm*Cc];
__device__ __nv_bfloat16 g_Wqh[(size_t)C3*Cc], g_Wql[(size_t)C3*Cc];
__device__ __nv_bfloat16 g_Wph[(size_t)Cc*Cc], g_Wpl[(size_t)Cc*Cc];

// ---------------------------------------------------------------------------
// helpers
// ---------------------------------------------------------------------------
__device__ __forceinline__ uint32_t smem_u32(const void* p) {
    uint32_t a;
    asm("{ .reg .u64 t; cvta.to.shared.u64 t, %1; cvt.u32.u64 %0, t; }"
        : "=r"(a) : "l"(p));
    return a;
}
__device__ __forceinline__ void cpa16(uint32_t dst, const void* src) {
    asm volatile("cp.async.cg.shared.global [%0], [%1], 16;" :: "r"(dst), "l"(src));
}
__device__ __forceinline__ void cp_commit() {
    asm volatile("cp.async.commit_group;" ::: "memory");
}
template <int N>
__device__ __forceinline__ void cp_wait() {
    asm volatile("cp.async.wait_group %0;" :: "n"(N) : "memory");
}
__device__ __forceinline__ void ldsm4(uint32_t* r, uint32_t addr) {
    asm volatile("ldmatrix.sync.aligned.m8n8.x4.shared.b16 {%0,%1,%2,%3}, [%4];"
                 : "=r"(r[0]), "=r"(r[1]), "=r"(r[2]), "=r"(r[3]) : "r"(addr));
}
__device__ __forceinline__ void mma16816(float* d, const uint32_t* a, const uint32_t* b) {
    asm volatile(
        "mma.sync.aligned.m16n8k16.row.col.f32.bf16.bf16.f32 "
        "{%0,%1,%2,%3}, {%4,%5,%6,%7}, {%8,%9}, {%0,%1,%2,%3};"
        : "+f"(d[0]), "+f"(d[1]), "+f"(d[2]), "+f"(d[3])
        : "r"(a[0]), "r"(a[1]), "r"(a[2]), "r"(a[3]), "r"(b[0]), "r"(b[1]));
}

// ---------------------------------------------------------------------------
// K1: per-channel partial sums (deterministic, no atomics)
// ---------------------------------------------------------------------------
__global__ void bn_partial(const float* __restrict__ x) {
    int c = blockIdx.x * 128 + threadIdx.x;
    int chunk = blockIdx.y;
    const int RPC = Mm / RCH;
    const float* p = x + (size_t)(chunk * RPC) * Cc + c;
    float s = 0.f, sq = 0.f;
    for (int r = 0; r < RPC; r++) { float v = p[(size_t)r * Cc]; s += v; sq += v * v; }
    g_psum[chunk * Cc + c] = s;
    g_psq[chunk * Cc + c]  = sq;
}

// ---------------------------------------------------------------------------
// K2: finalize BN affine + softplus(scale_p)
// ---------------------------------------------------------------------------
__global__ void bn_finalize(const float* __restrict__ gamma,
                            const float* __restrict__ beta,
                            const float* __restrict__ scale_p) {
    int c = blockIdx.x * 256 + threadIdx.x;
    float s = 0.f, sq = 0.f;
    for (int i = 0; i < RCH; i++) { s += g_psum[i * Cc + c]; sq += g_psq[i * Cc + c]; }
    float mean = s / (float)Mm;
    float var  = sq / (float)Mm - mean * mean;
    float rstd = rsqrtf(var + 1e-5f);
    float a = rstd * gamma[c];
    g_bn_a[c] = a;
    g_bn_b[c] = beta[c] - mean * a;
    float sp = scale_p[c];
    g_scale[c] = (sp > 20.f) ? sp : log1pf(expf(sp));
}

// ---------------------------------------------------------------------------
// K3: xn = BN(x), split to bf16 hi/lo
// ---------------------------------------------------------------------------
__global__ void prep_x(const float* __restrict__ x) {
    size_t i = (size_t)blockIdx.x * 256 + threadIdx.x;   // float4 index
    float4 v = ((const float4*)x)[i];
    int c = (int)((i * 4) & (Cc - 1));
    v.x = v.x * g_bn_a[c]     + g_bn_b[c];
    v.y = v.y * g_bn_a[c + 1] + g_bn_b[c + 1];
    v.z = v.z * g_bn_a[c + 2] + g_bn_b[c + 2];
    v.w = v.w * g_bn_a[c + 3] + g_bn_b[c + 3];
    __nv_bfloat16 hx = __float2bfloat16(v.x), hy = __float2bfloat16(v.y);
    __nv_bfloat16 hz = __float2bfloat16(v.z), hw = __float2bfloat16(v.w);
    __nv_bfloat162* ph = (__nv_bfloat162*)g_Ahi;
    __nv_bfloat162* pl = (__nv_bfloat162*)g_Alo;
    ph[i * 2]     = {hx, hy};
    ph[i * 2 + 1] = {hz, hw};
    pl[i * 2]     = {__float2bfloat16(v.x - __bfloat162float(hx)),
                     __float2bfloat16(v.y - __bfloat162float(hy))};
    pl[i * 2 + 1] = {__float2bfloat16(v.z - __bfloat162float(hz)),
                     __float2bfloat16(v.w - __bfloat162float(hw))};
}

// ---------------------------------------------------------------------------
// K4: transpose W [K=1024, Nout] -> Wt [Nout, 1024] split to bf16 hi/lo
// ---------------------------------------------------------------------------
__global__ void prep_w(const float* __restrict__ W,
                       __nv_bfloat16* __restrict__ hi, __nv_bfloat16* __restrict__ lo,
                       int Nout) {
    __shared__ float tile[32][33];
    int n0 = blockIdx.x * 32, k0 = blockIdx.y * 32;
    int tx = threadIdx.x, ty = threadIdx.y;     // (32, 8)
#pragma unroll
    for (int j = 0; j < 32; j += 8)
        tile[ty + j][tx] = W[(size_t)(k0 + ty + j) * Nout + n0 + tx];
    __syncthreads();
#pragma unroll
    for (int j = 0; j < 32; j += 8) {
        float v = tile[tx][ty + j];
        size_t oi = (size_t)(n0 + ty + j) * Cc + k0 + tx;
        __nv_bfloat16 h = __float2bfloat16(v);
        hi[oi] = h;
        lo[oi] = __float2bfloat16(v - __bfloat162float(h));
    }
}

// ---------------------------------------------------------------------------
// K5: HMMA GEMM  C[M,Ndim] = A @ Bt^T + bias  (3-term bf16 Markidis)
// A: [M,1024] bf16 hi/lo row-major; Bt: [Ndim,1024] bf16 hi/lo row-major.
// BM=BN=128, BK=32. 8 warps, warp tile 32x64. cp.async 2-stage pipeline.
// smem rows padded to 80B (conflict-free ldmatrix). 
// ---------------------------------------------------------------------------
#define SROW 80
#define T_AH 0
#define T_AL 10240
#define T_BH 20480
#define T_BL 30720
#define STG  40960

__global__ __launch_bounds__(256, 1)
void gemm_mma(const __nv_bfloat16* __restrict__ Ahi, const __nv_bfloat16* __restrict__ Alo,
              const __nv_bfloat16* __restrict__ Bhi, const __nv_bfloat16* __restrict__ Blo,
              const float* __restrict__ bias, float* __restrict__ Cout, int Ndim) {
    extern __shared__ char sm[];
    const int t = threadIdx.x;
    const int wid = t >> 5, lane = t & 31;
    const int m0 = blockIdx.y * 128, n0 = blockIdx.x * 128;
    const int warp_m = wid & 3, warp_n = wid >> 2;   // 4 x 2 warp grid
    const uint32_t sb = smem_u32(sm);

    float acc[2][8][4];
#pragma unroll
    for (int i = 0; i < 2; i++)
#pragma unroll
        for (int j = 0; j < 8; j++)
#pragma unroll
            for (int q = 0; q < 4; q++) acc[i][j][q] = 0.f;

    // per-thread load assignment: 2 chunks of 16B per tile per stage
    int id0 = t, id1 = t + 256;
    int r0g = id0 >> 2, c0g = id0 & 3;
    int r1g = id1 >> 2, c1g = id1 & 3;
    uint32_t d0 = (uint32_t)r0g * SROW + c0g * 16;
    uint32_t d1 = (uint32_t)r1g * SROW + c1g * 16;

#define LOAD_STAGE(IT)                                                          \
    {                                                                           \
        int k0_ = (IT) * 32;                                                    \
        uint32_t dst = sb + ((IT) & 1) * STG;                                   \
        cpa16(dst + T_AH + d0, Ahi + (size_t)(m0 + r0g) * Cc + k0_ + c0g * 8);  \
        cpa16(dst + T_AH + d1, Ahi + (size_t)(m0 + r1g) * Cc + k0_ + c1g * 8);  \
        cpa16(dst + T_AL + d0, Alo + (size_t)(m0 + r0g) * Cc + k0_ + c0g * 8);  \
        cpa16(dst + T_AL + d1, Alo + (size_t)(m0 + r1g) * Cc + k0_ + c1g * 8);  \
        cpa16(dst + T_BH + d0, Bhi + (size_t)(n0 + r0g) * Cc + k0_ + c0g * 8);  \
        cpa16(dst + T_BH + d1, Bhi + (size_t)(n0 + r1g) * Cc + k0_ + c1g * 8);  \
        cpa16(dst + T_BL + d0, Blo + (size_t)(n0 + r0g) * Cc + k0_ + c0g * 8);  \
        cpa16(dst + T_BL + d1, Blo + (size_t)(n0 + r1g) * Cc + k0_ + c1g * 8);  \
        cp_commit();                                                            \
    }

    LOAD_STAGE(0)
    LOAD_STAGE(1)

    // ldmatrix address components (within a 128x32 tile, 80B row stride)
    const uint32_t a_off = (uint32_t)(warp_m * 32 + (lane & 15)) * SROW + ((lane >> 4) << 3) * 2;
    const uint32_t b_off = (uint32_t)(warp_n * 64 + ((lane & 16) >> 1) + (lane & 7)) * SROW + (lane & 8) * 2;

    for (int it = 0; it < 32; it++) {
        if (it < 31) cp_wait<1>(); else cp_wait<0>();
        __syncthreads();

        uint32_t base = sb + (it & 1) * STG;
#pragma unroll
        for (int kk2 = 0; kk2 < 2; kk2++) {
            uint32_t ko = kk2 * 32;   // 16 bf16 = 32 bytes
            uint32_t ah[2][4], al[2][4], bh[4][4], bl[4][4];
            ldsm4(ah[0], base + T_AH + a_off + ko);
            ldsm4(ah[1], base + T_AH + a_off + ko + 16 * SROW);
            ldsm4(al[0], base + T_AL + a_off + ko);
            ldsm4(al[1], base + T_AL + a_off + ko + 16 * SROW);
#pragma unroll
            for (int nt2 = 0; nt2 < 4; nt2++) {
                ldsm4(bh[nt2], base + T_BH + b_off + ko + nt2 * 16 * SROW);
                ldsm4(bl[nt2], base + T_BL + b_off + ko + nt2 * 16 * SROW);
            }
#pragma unroll
            for (int mt = 0; mt < 2; mt++)
#pragma unroll
                for (int nt = 0; nt < 8; nt++) {
                    const uint32_t* bhp = &bh[nt >> 1][(nt & 1) * 2];
                    const uint32_t* blp = &bl[nt >> 1][(nt & 1) * 2];
                    mma16816(acc[mt][nt], ah[mt], bhp);
                    mma16816(acc[mt][nt], ah[mt], blp);
                    mma16816(acc[mt][nt], al[mt], bhp);
                }
        }
        __syncthreads();
        if (it + 2 < 32) LOAD_STAGE(it + 2)
    }

    // epilogue: add bias, store float2 per (mt, nt)
#pragma unroll
    for (int mt = 0; mt < 2; mt++) {
        int row = m0 + warp_m * 32 + mt * 16 + (lane >> 2);
#pragma unroll
        for (int nt = 0; nt < 8; nt++) {
            int col = n0 + warp_n * 64 + nt * 8 + (lane & 3) * 2;
            float b0 = bias[col], b1 = bias[col + 1];
            float2* p0 = (float2*)(Cout + (size_t)row * Ndim + col);
            float2* p1 = (float2*)(Cout + (size_t)(row + 8) * Ndim + col);
            *p0 = {acc[mt][nt][0] + b0, acc[mt][nt][1] + b1};
            *p1 = {acc[mt][nt][2] + b0, acc[mt][nt][3] + b1};
        }
    }
}

// ---------------------------------------------------------------------------
// K6: focused feature map, in place on q / k rows
// ---------------------------------------------------------------------------
__global__ void focus_kernel() {
    int bx  = blockIdx.x;
    int m   = bx >> 1;
    int sel = bx & 1;
    float* p = g_qkv + (size_t)m * C3 + sel * Cc;
    int t = threadIdx.x;

    float t3[4];
    float s2 = 0.f, s6 = 0.f;
#pragma unroll
    for (int i = 0; i < 4; i++) {
        int c = t + i * 256;
        float v = fmaxf(p[c], 0.f) + 1e-6f;
        v = v / g_scale[c];
        s2 += v * v;
        float v3 = v * v * v;
        t3[i] = v3;
        s6 += v3 * v3;
    }
    __shared__ float sh2[8], sh6[8];
#pragma unroll
    for (int off = 16; off; off >>= 1) {
        s2 += __shfl_xor_sync(0xffffffffu, s2, off);
        s6 += __shfl_xor_sync(0xffffffffu, s6, off);
    }
    int w = t >> 5, lane = t & 31;
    if (lane == 0) { sh2[w] = s2; sh6[w] = s6; }
    __syncthreads();
    if (t == 0) {
        float a = 0.f, b = 0.f;
        for (int i = 0; i < 8; i++) { a += sh2[i]; b += sh6[i]; }
        sh2[0] = a; sh6[0] = b;
    }
    __syncthreads();
    float factor = sqrtf(sh2[0] / sh6[0]);
#pragma unroll
    for (int i = 0; i < 4; i++) p[t + i * 256] = t3[i] * factor;
}

// ---------------------------------------------------------------------------
// K7: per (b,h): kv[d][e] = sum_n k[n,d] v[n,e]; ksum[d] = sum_n k[n,d]
// ---------------------------------------------------------------------------
__global__ __launch_bounds__(256) void kv_kernel() {
    int bh = blockIdx.x;
    int b = bh >> 4, h = bh & 15;
    const float* kbase = g_qkv + (size_t)(b * Nn) * C3 + Cc + h * Dd;
    const float* vbase = kbase + Cc;

    __shared__ float ks[32][65], vs[32][65];
    int t = threadIdx.x;
    int dr = (t >> 4) << 2, ec = (t & 15) << 2;

    float acc[4][4];
#pragma unroll
    for (int i = 0; i < 4; i++)
#pragma unroll
        for (int j = 0; j < 4; j++) acc[i][j] = 0.f;
    float ksacc = 0.f;

    for (int n0 = 0; n0 < Nn; n0 += 32) {
        __syncthreads();
#pragma unroll
        for (int i = 0; i < 8; i++) {
            int idx = t + i * 256;
            int r = idx >> 6, c = idx & 63;
            ks[r][c] = kbase[(size_t)(n0 + r) * C3 + c];
            vs[r][c] = vbase[(size_t)(n0 + r) * C3 + c];
        }
        __syncthreads();
#pragma unroll 8
        for (int n = 0; n < 32; n++) {
            float kd0 = ks[n][dr], kd1 = ks[n][dr + 1], kd2 = ks[n][dr + 2], kd3 = ks[n][dr + 3];
            float v0 = vs[n][ec], v1 = vs[n][ec + 1], v2 = vs[n][ec + 2], v3 = vs[n][ec + 3];
            acc[0][0] += kd0 * v0; acc[0][1] += kd0 * v1; acc[0][2] += kd0 * v2; acc[0][3] += kd0 * v3;
            acc[1][0] += kd1 * v0; acc[1][1] += kd1 * v1; acc[1][2] += kd1 * v2; acc[1][3] += kd1 * v3;
            acc[2][0] += kd2 * v0; acc[2][1] += kd2 * v1; acc[2][2] += kd2 * v2; acc[2][3] += kd2 * v3;
            acc[3][0] += kd3 * v0; acc[3][1] += kd3 * v1; acc[3][2] += kd3 * v2; acc[3][3] += kd3 * v3;
        }
        if (t < 64) {
#pragma unroll 8
            for (int n = 0; n < 32; n++) ksacc += ks[n][t];
        }
    }

    float* kvout = g_kv + bh * (Dd * Dd);
#pragma unroll
    for (int i = 0; i < 4; i++)
#pragma unroll
        for (int j = 0; j < 4; j++)
            kvout[(dr + i) * Dd + ec + j] = acc[i][j];
    if (t < 64) g_ksum[bh * Dd + t] = ksacc;
}

// ---------------------------------------------------------------------------
// K8: o = (q @ kv) * z fused with depthwise conv; writes bf16 hi/lo for proj
// ---------------------------------------------------------------------------
__global__ __launch_bounds__(256) void o_dwc_kernel(const float* __restrict__ dwc_w,
                                                    const float* __restrict__ dwc_b) {
    int bh = blockIdx.x;
    int b = bh >> 4, h = bh & 15;
    int n0 = blockIdx.y * 128;

    __shared__ float kvs[64][65];
    __shared__ float ksums[64];
    __shared__ float qrow[8][64];

    int t = threadIdx.x;
    int w = t >> 5, lane = t & 31;

#pragma unroll
    for (int i = 0; i < 16; i++) {
        int idx = t + i * 256;
        kvs[idx >> 6][idx & 63] = g_kv[bh * (Dd * Dd) + idx];
    }
    if (t < 64) ksums[t] = g_ksum[bh * Dd + t];
    __syncthreads();

    const float* qbase = g_qkv + (size_t)(b * Nn) * C3 + h * Dd;
    const float* vbase = g_qkv + (size_t)(b * Nn) * C3 + 2 * Cc + h * Dd;

    int c0 = h * 64 + lane, c1 = h * 64 + lane + 32;
    float w0[5], w1[5];
#pragma unroll
    for (int j = 0; j < 5; j++) { w0[j] = dwc_w[c0 * 5 + j]; w1[j] = dwc_w[c1 * 5 + j]; }
    float db0 = dwc_b[c0], db1 = dwc_b[c1];

    for (int r = w; r < 128; r += 8) {
        int n = n0 + r;
        const float* qp = qbase + (size_t)n * C3;
        qrow[w][lane]      = qp[lane];
        qrow[w][lane + 32] = qp[lane + 32];
        __syncwarp();

        float s = qrow[w][lane] * ksums[lane] + qrow[w][lane + 32] * ksums[lane + 32];
#pragma unroll
        for (int off = 16; off; off >>= 1) s += __shfl_xor_sync(0xffffffffu, s, off);
        float z = 1.f / (s + 1e-6f);

        float acc0 = 0.f, acc1 = 0.f;
#pragma unroll
        for (int d = 0; d < 64; d++) {
            float qd = qrow[w][d];
            acc0 += qd * kvs[d][lane];
            acc1 += qd * kvs[d][lane + 32];
        }

        float dw0 = db0, dw1 = db1;
#pragma unroll
        for (int j = 0; j < 5; j++) {
            int nn = n + j - 2;
            if ((unsigned)nn < (unsigned)Nn) {
                const float* vp = vbase + (size_t)nn * C3;
                dw0 += vp[lane]      * w0[j];
                dw1 += vp[lane + 32] * w1[j];
            }
        }

        float o0 = acc0 * z + dw0;
        float o1 = acc1 * z + dw1;
        size_t oi = (size_t)(b * Nn + n) * Cc + h * 64;
        __nv_bfloat16 h0 = __float2bfloat16(o0);
        __nv_bfloat16 h1 = __float2bfloat16(o1);
        g_Ohi[oi + lane]      = h0;
        g_Ohi[oi + lane + 32] = h1;
        g_Olo[oi + lane]      = __float2bfloat16(o0 - __bfloat162float(h0));
        g_Olo[oi + lane + 32] = __float2bfloat16(o1 - __bfloat162float(h1));
        __syncwarp();
    }
}

// ---------------------------------------------------------------------------
extern "C" void kernel_launch(void* const* d_in, const int* in_sizes, int n_in,
                              void* d_out, int out_size) {
    const float* x       = (const float*)d_in[0];
    const float* gamma   = (const float*)d_in[1];
    const float* beta    = (const float*)d_in[2];
    const float* Wqkv    = (const float*)d_in[3];
    const float* bqkv    = (const float*)d_in[4];
    const float* scale_p = (const float*)d_in[5];
    const float* dwc_w   = (const float*)d_in[6];
    const float* dwc_b   = (const float*)d_in[7];
    const float* Wproj   = (const float*)d_in[8];
    const float* bproj   = (const float*)d_in[9];
    float* out = (float*)d_out;

    void *p_qkv, *p_Ahi, *p_Alo, *p_Ohi, *p_Olo, *p_Wqh, *p_Wql, *p_Wph, *p_Wpl;
    cudaGetSymbolAddress(&p_qkv, g_qkv);
    cudaGetSymbolAddress(&p_Ahi, g_Ahi);
    cudaGetSymbolAddress(&p_Alo, g_Alo);
    cudaGetSymbolAddress(&p_Ohi, g_Ohi);
    cudaGetSymbolAddress(&p_Olo, g_Olo);
    cudaGetSymbolAddress(&p_Wqh, g_Wqh);
    cudaGetSymbolAddress(&p_Wql, g_Wql);
    cudaGetSymbolAddress(&p_Wph, g_Wph);
    cudaGetSymbolAddress(&p_Wpl, g_Wpl);

    const int SMEM_GEMM = 2 * STG;   // 81920 bytes
    static int attr_done = 0;
    if (!attr_done) {
        cudaFuncSetAttribute(gemm_mma, cudaFuncAttributeMaxDynamicSharedMemorySize, SMEM_GEMM);
        attr_done = 1;
    }

    // 1. BN stats
    bn_partial<<<dim3(8, RCH), 128>>>(x);
    bn_finalize<<<4, 256>>>(gamma, beta, scale_p);

    // 2. operand prep: BN(x) -> bf16 hi/lo; transpose+split weights
    prep_x<<<(Mm * Cc / 4) / 256, 256>>>(x);
    prep_w<<<dim3(C3 / 32, Cc / 32), dim3(32, 8)>>>(Wqkv, (__nv_bfloat16*)p_Wqh, (__nv_bfloat16*)p_Wql, C3);
    prep_w<<<dim3(Cc / 32, Cc / 32), dim3(32, 8)>>>(Wproj, (__nv_bfloat16*)p_Wph, (__nv_bfloat16*)p_Wpl, Cc);

    // 3. QKV GEMM (HMMA): [16384,1024] @ [1024,3072] + bias
    gemm_mma<<<dim3(C3 / 128, Mm / 128), 256, SMEM_GEMM>>>(
        (const __nv_bfloat16*)p_Ahi, (const __nv_bfloat16*)p_Alo,
        (const __nv_bfloat16*)p_Wqh, (const __nv_bfloat16*)p_Wql,
        bqkv, (float*)p_qkv, C3);

    // 4. focus(q), focus(k) in place
    focus_kernel<<<2 * Mm, 256>>>();

    // 5. per-(b,h) K^T V and k-sum
    kv_kernel<<<Bb * Hh, 256>>>();

    // 6. o = (q @ kv) * z + dwc residual -> bf16 hi/lo
    o_dwc_kernel<<<dim3(Bb * Hh, Nn / 128), 256>>>(dwc_w, dwc_b);

    // 7. proj GEMM (HMMA): [16384,1024] @ [1024,1024] + bias -> out
    gemm_mma<<<dim3(Cc / 128, Mm / 128), 256, SMEM_GEMM>>>(
        (const __nv_bfloat16*)p_Ohi, (const __nv_bfloat16*)p_Olo,
        (const __nv_bfloat16*)p_Wph, (const __nv_bfloat16*)p_Wpl,
        bproj, out, Cc);
}

// round 5
// speedup vs baseline: 2.0157x; 1.0277x over previous
#include <cuda_runtime.h>
#include <cuda_bf16.h>
#include <math.h>
#include <stdint.h>

#define Bb 8
#define Nn 2048
#define Cc 1024
#define Hh 16
#define Dd 64
#define Mm (Bb*Nn)      /* 16384 */
#define C3 (3*Cc)       /* 3072  */
#define RCH 64

// ---- scratch (static device globals; no allocations allowed) ----
__device__ float g_qkv[(size_t)Mm*C3];     // q|k|v per row (f32)
__device__ float g_kv[Bb*Hh*Dd*Dd];
__device__ float g_ksum[Bb*Hh*Dd];
__device__ float g_bn_a[Cc], g_bn_b[Cc], g_rscale[Cc];
__device__ float g_psum[RCH*Cc], g_psq[RCH*Cc];
// bf16 hi/lo split operands for tensor-core GEMMs
__device__ __nv_bfloat16 g_Ahi[(size_t)Mm*Cc], g_Alo[(size_t)Mm*Cc];
__device__ __nv_bfloat16 g_Ohi[(size_t)Mm*Cc], g_Olo[(size_t)Mm*Cc];
__device__ __nv_bfloat16 g_Wqh[(size_t)C3*Cc], g_Wql[(size_t)C3*Cc];
__device__ __nv_bfloat16 g_Wph[(size_t)Cc*Cc], g_Wpl[(size_t)Cc*Cc];

// ---------------------------------------------------------------------------
// helpers
// ---------------------------------------------------------------------------
__device__ __forceinline__ uint32_t smem_u32(const void* p) {
    uint32_t a;
    asm("{ .reg .u64 t; cvta.to.shared.u64 t, %1; cvt.u32.u64 %0, t; }"
        : "=r"(a) : "l"(p));
    return a;
}
__device__ __forceinline__ void cpa16(uint32_t dst, const void* src) {
    asm volatile("cp.async.cg.shared.global [%0], [%1], 16;" :: "r"(dst), "l"(src));
}
__device__ __forceinline__ void cp_commit() {
    asm volatile("cp.async.commit_group;" ::: "memory");
}
template <int N>
__device__ __forceinline__ void cp_wait() {
    asm volatile("cp.async.wait_group %0;" :: "n"(N) : "memory");
}
__device__ __forceinline__ void ldsm4(uint32_t* r, uint32_t addr) {
    asm volatile("ldmatrix.sync.aligned.m8n8.x4.shared.b16 {%0,%1,%2,%3}, [%4];"
                 : "=r"(r[0]), "=r"(r[1]), "=r"(r[2]), "=r"(r[3]) : "r"(addr));
}
__device__ __forceinline__ void mma16816(float* d, const uint32_t* a, const uint32_t* b) {
    asm volatile(
        "mma.sync.aligned.m16n8k16.row.col.f32.bf16.bf16.f32 "
        "{%0,%1,%2,%3}, {%4,%5,%6,%7}, {%8,%9}, {%0,%1,%2,%3};"
        : "+f"(d[0]), "+f"(d[1]), "+f"(d[2]), "+f"(d[3])
        : "r"(a[0]), "r"(a[1]), "r"(a[2]), "r"(a[3]), "r"(b[0]), "r"(b[1]));
}

// ---------------------------------------------------------------------------
// K1: per-channel partial sums (deterministic, no atomics)
// ---------------------------------------------------------------------------
__global__ void bn_partial(const float* __restrict__ x) {
    int c = blockIdx.x * 128 + threadIdx.x;
    int chunk = blockIdx.y;
    const int RPC = Mm / RCH;
    const float* p = x + (size_t)(chunk * RPC) * Cc + c;
    float s = 0.f, sq = 0.f;
    for (int r = 0; r < RPC; r++) { float v = p[(size_t)r * Cc]; s += v; sq += v * v; }
    g_psum[chunk * Cc + c] = s;
    g_psq[chunk * Cc + c]  = sq;
}

// ---------------------------------------------------------------------------
// K2: finalize BN affine + reciprocal softplus(scale_p)
// ---------------------------------------------------------------------------
__global__ void bn_finalize(const float* __restrict__ gamma,
                            const float* __restrict__ beta,
                            const float* __restrict__ scale_p) {
    int c = blockIdx.x * 256 + threadIdx.x;
    float s = 0.f, sq = 0.f;
    for (int i = 0; i < RCH; i++) { s += g_psum[i * Cc + c]; sq += g_psq[i * Cc + c]; }
    float mean = s / (float)Mm;
    float var  = sq / (float)Mm - mean * mean;
    float rstd = rsqrtf(var + 1e-5f);
    float a = rstd * gamma[c];
    g_bn_a[c] = a;
    g_bn_b[c] = beta[c] - mean * a;
    float sp = scale_p[c];
    float sc = (sp > 20.f) ? sp : log1pf(expf(sp));
    g_rscale[c] = 1.0f / sc;
}

// ---------------------------------------------------------------------------
// K3: xn = BN(x), split to bf16 hi/lo
// ---------------------------------------------------------------------------
__global__ void prep_x(const float* __restrict__ x) {
    size_t i = (size_t)blockIdx.x * 256 + threadIdx.x;   // float4 index
    float4 v = ((const float4*)x)[i];
    int c = (int)((i * 4) & (Cc - 1));
    v.x = v.x * g_bn_a[c]     + g_bn_b[c];
    v.y = v.y * g_bn_a[c + 1] + g_bn_b[c + 1];
    v.z = v.z * g_bn_a[c + 2] + g_bn_b[c + 2];
    v.w = v.w * g_bn_a[c + 3] + g_bn_b[c + 3];
    __nv_bfloat16 hx = __float2bfloat16(v.x), hy = __float2bfloat16(v.y);
    __nv_bfloat16 hz = __float2bfloat16(v.z), hw = __float2bfloat16(v.w);
    __nv_bfloat162* ph = (__nv_bfloat162*)g_Ahi;
    __nv_bfloat162* pl = (__nv_bfloat162*)g_Alo;
    ph[i * 2]     = {hx, hy};
    ph[i * 2 + 1] = {hz, hw};
    pl[i * 2]     = {__float2bfloat16(v.x - __bfloat162float(hx)),
                     __float2bfloat16(v.y - __bfloat162float(hy))};
    pl[i * 2 + 1] = {__float2bfloat16(v.z - __bfloat162float(hz)),
                     __float2bfloat16(v.w - __bfloat162float(hw))};
}

// ---------------------------------------------------------------------------
// K4: transpose W [K=1024, Nout] -> Wt [Nout, 1024] split to bf16 hi/lo
// ---------------------------------------------------------------------------
__global__ void prep_w(const float* __restrict__ W,
                       __nv_bfloat16* __restrict__ hi, __nv_bfloat16* __restrict__ lo,
                       int Nout) {
    __shared__ float tile[32][33];
    int n0 = blockIdx.x * 32, k0 = blockIdx.y * 32;
    int tx = threadIdx.x, ty = threadIdx.y;     // (32, 8)
#pragma unroll
    for (int j = 0; j < 32; j += 8)
        tile[ty + j][tx] = W[(size_t)(k0 + ty + j) * Nout + n0 + tx];
    __syncthreads();
#pragma unroll
    for (int j = 0; j < 32; j += 8) {
        float v = tile[tx][ty + j];
        size_t oi = (size_t)(n0 + ty + j) * Cc + k0 + tx;
        __nv_bfloat16 h = __float2bfloat16(v);
        hi[oi] = h;
        lo[oi] = __float2bfloat16(v - __bfloat162float(h));
    }
}

// ---------------------------------------------------------------------------
// K5: HMMA GEMM  C[M,Ndim] = A @ Bt^T + bias  (3-term bf16 Markidis)
// BM=BN=128, BK=32. 8 warps, warp tile 32x64. cp.async 4-stage pipeline,
// one __syncthreads per K-iter. smem rows padded to 80B (conflict-free).
// ---------------------------------------------------------------------------
#define SROW 80
#define T_AH 0
#define T_AL 10240
#define T_BH 20480
#define T_BL 30720
#define STG  40960
#define NSTAGE 4

__global__ __launch_bounds__(256, 1)
void gemm_mma(const __nv_bfloat16* __restrict__ Ahi, const __nv_bfloat16* __restrict__ Alo,
              const __nv_bfloat16* __restrict__ Bhi, const __nv_bfloat16* __restrict__ Blo,
              const float* __restrict__ bias, float* __restrict__ Cout, int Ndim) {
    extern __shared__ char sm[];
    const int t = threadIdx.x;
    const int wid = t >> 5, lane = t & 31;
    const int m0 = blockIdx.y * 128, n0 = blockIdx.x * 128;
    const int warp_m = wid & 3, warp_n = wid >> 2;   // 4 x 2 warp grid
    const uint32_t sb = smem_u32(sm);

    float acc[2][8][4];
#pragma unroll
    for (int i = 0; i < 2; i++)
#pragma unroll
        for (int j = 0; j < 8; j++)
#pragma unroll
            for (int q = 0; q < 4; q++) acc[i][j][q] = 0.f;

    // per-thread load assignment: 2 chunks of 16B per tile per stage
    int id0 = t, id1 = t + 256;
    int r0g = id0 >> 2, c0g = id0 & 3;
    int r1g = id1 >> 2, c1g = id1 & 3;
    uint32_t d0 = (uint32_t)r0g * SROW + c0g * 16;
    uint32_t d1 = (uint32_t)r1g * SROW + c1g * 16;

#define LOAD_STAGE(IT)                                                          \
    {                                                                           \
        int k0_ = (IT) * 32;                                                    \
        uint32_t dst = sb + ((IT) & (NSTAGE - 1)) * STG;                        \
        cpa16(dst + T_AH + d0, Ahi + (size_t)(m0 + r0g) * Cc + k0_ + c0g * 8);  \
        cpa16(dst + T_AH + d1, Ahi + (size_t)(m0 + r1g) * Cc + k0_ + c1g * 8);  \
        cpa16(dst + T_AL + d0, Alo + (size_t)(m0 + r0g) * Cc + k0_ + c0g * 8);  \
        cpa16(dst + T_AL + d1, Alo + (size_t)(m0 + r1g) * Cc + k0_ + c1g * 8);  \
        cpa16(dst + T_BH + d0, Bhi + (size_t)(n0 + r0g) * Cc + k0_ + c0g * 8);  \
        cpa16(dst + T_BH + d1, Bhi + (size_t)(n0 + r1g) * Cc + k0_ + c1g * 8);  \
        cpa16(dst + T_BL + d0, Blo + (size_t)(n0 + r0g) * Cc + k0_ + c0g * 8);  \
        cpa16(dst + T_BL + d1, Blo + (size_t)(n0 + r1g) * Cc + k0_ + c1g * 8);  \
        cp_commit();                                                            \
    }

    LOAD_STAGE(0)
    LOAD_STAGE(1)
    LOAD_STAGE(2)

    // ldmatrix address components (within a 128x32 tile, 80B row stride)
    const uint32_t a_off = (uint32_t)(warp_m * 32 + (lane & 15)) * SROW + ((lane >> 4) << 3) * 2;
    const uint32_t b_off = (uint32_t)(warp_n * 64 + ((lane & 16) >> 1) + (lane & 7)) * SROW + (lane & 8) * 2;

    for (int it = 0; it < 32; it++) {
        // wait for stage `it` (newest 2 groups may still be in flight)
        cp_wait<2>();
        __syncthreads();
        // prefetch stage it+3 into the buffer consumed at iter it-1 (safe: all
        // threads passed the barrier above only after finishing compute it-1)
        if (it + 3 < 32) { LOAD_STAGE(it + 3) } else { cp_commit(); }

        uint32_t base = sb + (it & (NSTAGE - 1)) * STG;
#pragma unroll
        for (int kk2 = 0; kk2 < 2; kk2++) {
            uint32_t ko = kk2 * 32;   // 16 bf16 = 32 bytes
            uint32_t ah[2][4], al[2][4], bh[4][4], bl[4][4];
            ldsm4(ah[0], base + T_AH + a_off + ko);
            ldsm4(ah[1], base + T_AH + a_off + ko + 16 * SROW);
            ldsm4(al[0], base + T_AL + a_off + ko);
            ldsm4(al[1], base + T_AL + a_off + ko + 16 * SROW);
#pragma unroll
            for (int nt2 = 0; nt2 < 4; nt2++) {
                ldsm4(bh[nt2], base + T_BH + b_off + ko + nt2 * 16 * SROW);
                ldsm4(bl[nt2], base + T_BL + b_off + ko + nt2 * 16 * SROW);
            }
#pragma unroll
            for (int mt = 0; mt < 2; mt++)
#pragma unroll
                for (int nt = 0; nt < 8; nt++) {
                    const uint32_t* bhp = &bh[nt >> 1][(nt & 1) * 2];
                    const uint32_t* blp = &bl[nt >> 1][(nt & 1) * 2];
                    mma16816(acc[mt][nt], ah[mt], bhp);
                    mma16816(acc[mt][nt], ah[mt], blp);
                    mma16816(acc[mt][nt], al[mt], bhp);
                }
        }
    }

    // epilogue: add bias, store float2 per (mt, nt)
#pragma unroll
    for (int mt = 0; mt < 2; mt++) {
        int row = m0 + warp_m * 32 + mt * 16 + (lane >> 2);
#pragma unroll
        for (int nt = 0; nt < 8; nt++) {
            int col = n0 + warp_n * 64 + nt * 8 + (lane & 3) * 2;
            float b0 = bias[col], b1 = bias[col + 1];
            float2* p0 = (float2*)(Cout + (size_t)row * Ndim + col);
            float2* p1 = (float2*)(Cout + (size_t)(row + 8) * Ndim + col);
            *p0 = {acc[mt][nt][0] + b0, acc[mt][nt][1] + b1};
            *p1 = {acc[mt][nt][2] + b0, acc[mt][nt][3] + b1};
        }
    }
}

// ---------------------------------------------------------------------------
// K6: focused feature map, in place on q / k rows
// ---------------------------------------------------------------------------
__global__ void focus_kernel() {
    int bx  = blockIdx.x;
    int m   = bx >> 1;
    int sel = bx & 1;
    float* p = g_qkv + (size_t)m * C3 + sel * Cc;
    int t = threadIdx.x;

    float t3[4];
    float s2 = 0.f, s6 = 0.f;
#pragma unroll
    for (int i = 0; i < 4; i++) {
        int c = t + i * 256;
        float v = fmaxf(p[c], 0.f) + 1e-6f;
        v = v * g_rscale[c];
        s2 += v * v;
        float v3 = v * v * v;
        t3[i] = v3;
        s6 += v3 * v3;
    }
    __shared__ float sh2[8], sh6[8];
#pragma unroll
    for (int off = 16; off; off >>= 1) {
        s2 += __shfl_xor_sync(0xffffffffu, s2, off);
        s6 += __shfl_xor_sync(0xffffffffu, s6, off);
    }
    int w = t >> 5, lane = t & 31;
    if (lane == 0) { sh2[w] = s2; sh6[w] = s6; }
    __syncthreads();
    if (t == 0) {
        float a = 0.f, b = 0.f;
        for (int i = 0; i < 8; i++) { a += sh2[i]; b += sh6[i]; }
        sh2[0] = a; sh6[0] = b;
    }
    __syncthreads();
    float factor = sqrtf(sh2[0] / sh6[0]);
#pragma unroll
    for (int i = 0; i < 4; i++) p[t + i * 256] = t3[i] * factor;
}

// ---------------------------------------------------------------------------
// K7: per (b,h): kv[d][e] = sum_n k[n,d] v[n,e]; ksum[d] = sum_n k[n,d]
// ---------------------------------------------------------------------------
__global__ __launch_bounds__(256) void kv_kernel() {
    int bh = blockIdx.x;
    int b = bh >> 4, h = bh & 15;
    const float* kbase = g_qkv + (size_t)(b * Nn) * C3 + Cc + h * Dd;
    const float* vbase = kbase + Cc;

    __shared__ float ks[32][65], vs[32][65];
    int t = threadIdx.x;
    int dr = (t >> 4) << 2, ec = (t & 15) << 2;

    float acc[4][4];
#pragma unroll
    for (int i = 0; i < 4; i++)
#pragma unroll
        for (int j = 0; j < 4; j++) acc[i][j] = 0.f;
    float ksacc = 0.f;

    for (int n0 = 0; n0 < Nn; n0 += 32) {
        __syncthreads();
#pragma unroll
        for (int i = 0; i < 8; i++) {
            int idx = t + i * 256;
            int r = idx >> 6, c = idx & 63;
            ks[r][c] = kbase[(size_t)(n0 + r) * C3 + c];
            vs[r][c] = vbase[(size_t)(n0 + r) * C3 + c];
        }
        __syncthreads();
#pragma unroll 8
        for (int n = 0; n < 32; n++) {
            float kd0 = ks[n][dr], kd1 = ks[n][dr + 1], kd2 = ks[n][dr + 2], kd3 = ks[n][dr + 3];
            float v0 = vs[n][ec], v1 = vs[n][ec + 1], v2 = vs[n][ec + 2], v3 = vs[n][ec + 3];
            acc[0][0] += kd0 * v0; acc[0][1] += kd0 * v1; acc[0][2] += kd0 * v2; acc[0][3] += kd0 * v3;
            acc[1][0] += kd1 * v0; acc[1][1] += kd1 * v1; acc[1][2] += kd1 * v2; acc[1][3] += kd1 * v3;
            acc[2][0] += kd2 * v0; acc[2][1] += kd2 * v1; acc[2][2] += kd2 * v2; acc[2][3] += kd2 * v3;
            acc[3][0] += kd3 * v0; acc[3][1] += kd3 * v1; acc[3][2] += kd3 * v2; acc[3][3] += kd3 * v3;
        }
        if (t < 64) {
#pragma unroll 8
            for (int n = 0; n < 32; n++) ksacc += ks[n][t];
        }
    }

    float* kvout = g_kv + bh * (Dd * Dd);
#pragma unroll
    for (int i = 0; i < 4; i++)
#pragma unroll
        for (int j = 0; j < 4; j++)
            kvout[(dr + i) * Dd + ec + j] = acc[i][j];
    if (t < 64) g_ksum[bh * Dd + t] = ksacc;
}

// ---------------------------------------------------------------------------
// K8: o = (q @ kv) * z fused with depthwise conv; writes bf16 hi/lo for proj
// ---------------------------------------------------------------------------
__global__ __launch_bounds__(256) void o_dwc_kernel(const float* __restrict__ dwc_w,
                                                    const float* __restrict__ dwc_b) {
    int bh = blockIdx.x;
    int b = bh >> 4, h = bh & 15;
    int n0 = blockIdx.y * 128;

    __shared__ float kvs[64][65];
    __shared__ float ksums[64];
    __shared__ float qrow[8][64];

    int t = threadIdx.x;
    int w = t >> 5, lane = t & 31;

#pragma unroll
    for (int i = 0; i < 16; i++) {
        int idx = t + i * 256;
        kvs[idx >> 6][idx & 63] = g_kv[bh * (Dd * Dd) + idx];
    }
    if (t < 64) ksums[t] = g_ksum[bh * Dd + t];
    __syncthreads();

    const float* qbase = g_qkv + (size_t)(b * Nn) * C3 + h * Dd;
    const float* vbase = g_qkv + (size_t)(b * Nn) * C3 + 2 * Cc + h * Dd;

    int c0 = h * 64 + lane, c1 = h * 64 + lane + 32;
    float w0[5], w1[5];
#pragma unroll
    for (int j = 0; j < 5; j++) { w0[j] = dwc_w[c0 * 5 + j]; w1[j] = dwc_w[c1 * 5 + j]; }
    float db0 = dwc_b[c0], db1 = dwc_b[c1];

    for (int r = w; r < 128; r += 8) {
        int n = n0 + r;
        const float* qp = qbase + (size_t)n * C3;
        qrow[w][lane]      = qp[lane];
        qrow[w][lane + 32] = qp[lane + 32];
        __syncwarp();

        float s = qrow[w][lane] * ksums[lane] + qrow[w][lane + 32] * ksums[lane + 32];
#pragma unroll
        for (int off = 16; off; off >>= 1) s += __shfl_xor_sync(0xffffffffu, s, off);
        float z = 1.f / (s + 1e-6f);

        float acc0 = 0.f, acc1 = 0.f;
#pragma unroll
        for (int d = 0; d < 64; d++) {
            float qd = qrow[w][d];
            acc0 += qd * kvs[d][lane];
            acc1 += qd * kvs[d][lane + 32];
        }

        float dw0 = db0, dw1 = db1;
#pragma unroll
        for (int j = 0; j < 5; j++) {
            int nn = n + j - 2;
            if ((unsigned)nn < (unsigned)Nn) {
                const float* vp = vbase + (size_t)nn * C3;
                dw0 += vp[lane]      * w0[j];
                dw1 += vp[lane + 32] * w1[j];
            }
        }

        float o0 = acc0 * z + dw0;
        float o1 = acc1 * z + dw1;
        size_t oi = (size_t)(b * Nn + n) * Cc + h * 64;
        __nv_bfloat16 h0 = __float2bfloat16(o0);
        __nv_bfloat16 h1 = __float2bfloat16(o1);
        g_Ohi[oi + lane]      = h0;
        g_Ohi[oi + lane + 32] = h1;
        g_Olo[oi + lane]      = __float2bfloat16(o0 - __bfloat162float(h0));
        g_Olo[oi + lane + 32] = __float2bfloat16(o1 - __bfloat162float(h1));
        __syncwarp();
    }
}

// ---------------------------------------------------------------------------
extern "C" void kernel_launch(void* const* d_in, const int* in_sizes, int n_in,
                              void* d_out, int out_size) {
    const float* x       = (const float*)d_in[0];
    const float* gamma   = (const float*)d_in[1];
    const float* beta    = (const float*)d_in[2];
    const float* Wqkv    = (const float*)d_in[3];
    const float* bqkv    = (const float*)d_in[4];
    const float* scale_p = (const float*)d_in[5];
    const float* dwc_w   = (const float*)d_in[6];
    const float* dwc_b   = (const float*)d_in[7];
    const float* Wproj   = (const float*)d_in[8];
    const float* bproj   = (const float*)d_in[9];
    float* out = (float*)d_out;

    void *p_qkv, *p_Ahi, *p_Alo, *p_Ohi, *p_Olo, *p_Wqh, *p_Wql, *p_Wph, *p_Wpl;
    cudaGetSymbolAddress(&p_qkv, g_qkv);
    cudaGetSymbolAddress(&p_Ahi, g_Ahi);
    cudaGetSymbolAddress(&p_Alo, g_Alo);
    cudaGetSymbolAddress(&p_Ohi, g_Ohi);
    cudaGetSymbolAddress(&p_Olo, g_Olo);
    cudaGetSymbolAddress(&p_Wqh, g_Wqh);
    cudaGetSymbolAddress(&p_Wql, g_Wql);
    cudaGetSymbolAddress(&p_Wph, g_Wph);
    cudaGetSymbolAddress(&p_Wpl, g_Wpl);

    const int SMEM_GEMM = NSTAGE * STG;   // 163840 bytes
    static int attr_done = 0;
    if (!attr_done) {
        cudaFuncSetAttribute(gemm_mma, cudaFuncAttributeMaxDynamicSharedMemorySize, SMEM_GEMM);
        attr_done = 1;
    }

    // 1. BN stats
    bn_partial<<<dim3(8, RCH), 128>>>(x);
    bn_finalize<<<4, 256>>>(gamma, beta, scale_p);

    // 2. operand prep: BN(x) -> bf16 hi/lo; transpose+split weights
    prep_x<<<(Mm * Cc / 4) / 256, 256>>>(x);
    prep_w<<<dim3(C3 / 32, Cc / 32), dim3(32, 8)>>>(Wqkv, (__nv_bfloat16*)p_Wqh, (__nv_bfloat16*)p_Wql, C3);
    prep_w<<<dim3(Cc / 32, Cc / 32), dim3(32, 8)>>>(Wproj, (__nv_bfloat16*)p_Wph, (__nv_bfloat16*)p_Wpl, Cc);

    // 3. QKV GEMM (HMMA): [16384,1024] @ [1024,3072] + bias
    gemm_mma<<<dim3(C3 / 128, Mm / 128), 256, SMEM_GEMM>>>(
        (const __nv_bfloat16*)p_Ahi, (const __nv_bfloat16*)p_Alo,
        (const __nv_bfloat16*)p_Wqh, (const __nv_bfloat16*)p_Wql,
        bqkv, (float*)p_qkv, C3);

    // 4. focus(q), focus(k) in place
    focus_kernel<<<2 * Mm, 256>>>();

    // 5. per-(b,h) K^T V and k-sum
    kv_kernel<<<Bb * Hh, 256>>>();

    // 6. o = (q @ kv) * z + dwc residual -> bf16 hi/lo
    o_dwc_kernel<<<dim3(Bb * Hh, Nn / 128), 256>>>(dwc_w, dwc_b);

    // 7. proj GEMM (HMMA): [16384,1024] @ [1024,1024] + bias -> out
    gemm_mma<<<dim3(Cc / 128, Mm / 128), 256, SMEM_GEMM>>>(
        (const __nv_bfloat16*)p_Ohi, (const __nv_bfloat16*)p_Olo,
        (const __nv_bfloat16*)p_Wph, (const __nv_bfloat16*)p_Wpl,
        bproj, out, Cc);
}

// round 6
// speedup vs baseline: 2.1142x; 1.0489x over previous
#include <cuda_runtime.h>
#include <cuda_bf16.h>
#include <math.h>
#include <stdint.h>

#define Bb 8
#define Nn 2048
#define Cc 1024
#define Hh 16
#define Dd 64
#define Mm (Bb*Nn)      /* 16384 */
#define C3 (3*Cc)       /* 3072  */
#define RCH 64

// ---- scratch (static device globals; no allocations allowed) ----
__device__ float g_qkv[(size_t)Mm*C3];     // q|k|v per row (f32)
__device__ float g_kv[Bb*Hh*Dd*Dd];
__device__ float g_ksum[Bb*Hh*Dd];
__device__ float g_bn_a[Cc], g_bn_b[Cc], g_rscale[Cc];
__device__ float g_psum[RCH*Cc], g_psq[RCH*Cc];
// bf16 hi/lo split operands for tensor-core GEMMs
__device__ __nv_bfloat16 g_Ahi[(size_t)Mm*Cc], g_Alo[(size_t)Mm*Cc];
__device__ __nv_bfloat16 g_Ohi[(size_t)Mm*Cc], g_Olo[(size_t)Mm*Cc];
__device__ __nv_bfloat16 g_Wqh[(size_t)C3*Cc], g_Wql[(size_t)C3*Cc];
__device__ __nv_bfloat16 g_Wph[(size_t)Cc*Cc], g_Wpl[(size_t)Cc*Cc];

// ---------------------------------------------------------------------------
// helpers
// ---------------------------------------------------------------------------
__device__ __forceinline__ uint32_t smem_u32(const void* p) {
    uint32_t a;
    asm("{ .reg .u64 t; cvta.to.shared.u64 t, %1; cvt.u32.u64 %0, t; }"
        : "=r"(a) : "l"(p));
    return a;
}
__device__ __forceinline__ void cpa16(uint32_t dst, const void* src) {
    asm volatile("cp.async.cg.shared.global [%0], [%1], 16;" :: "r"(dst), "l"(src));
}
__device__ __forceinline__ void cp_commit() {
    asm volatile("cp.async.commit_group;" ::: "memory");
}
template <int N>
__device__ __forceinline__ void cp_wait() {
    asm volatile("cp.async.wait_group %0;" :: "n"(N) : "memory");
}
__device__ __forceinline__ void ldsm4(uint32_t* r, uint32_t addr) {
    asm volatile("ldmatrix.sync.aligned.m8n8.x4.shared.b16 {%0,%1,%2,%3}, [%4];"
                 : "=r"(r[0]), "=r"(r[1]), "=r"(r[2]), "=r"(r[3]) : "r"(addr));
}
__device__ __forceinline__ void mma16816(float* d, const uint32_t* a, const uint32_t* b) {
    asm volatile(
        "mma.sync.aligned.m16n8k16.row.col.f32.bf16.bf16.f32 "
        "{%0,%1,%2,%3}, {%4,%5,%6,%7}, {%8,%9}, {%0,%1,%2,%3};"
        : "+f"(d[0]), "+f"(d[1]), "+f"(d[2]), "+f"(d[3])
        : "r"(a[0]), "r"(a[1]), "r"(a[2]), "r"(a[3]), "r"(b[0]), "r"(b[1]));
}

// ---------------------------------------------------------------------------
// K1: per-channel partial sums (deterministic, no atomics)
// ---------------------------------------------------------------------------
__global__ void bn_partial(const float* __restrict__ x) {
    int c = blockIdx.x * 128 + threadIdx.x;
    int chunk = blockIdx.y;
    const int RPC = Mm / RCH;
    const float* p = x + (size_t)(chunk * RPC) * Cc + c;
    float s = 0.f, sq = 0.f;
    for (int r = 0; r < RPC; r++) { float v = p[(size_t)r * Cc]; s += v; sq += v * v; }
    g_psum[chunk * Cc + c] = s;
    g_psq[chunk * Cc + c]  = sq;
}

// ---------------------------------------------------------------------------
// K2: finalize BN affine + reciprocal softplus(scale_p)
// ---------------------------------------------------------------------------
__global__ void bn_finalize(const float* __restrict__ gamma,
                            const float* __restrict__ beta,
                            const float* __restrict__ scale_p) {
    int c = blockIdx.x * 256 + threadIdx.x;
    float s = 0.f, sq = 0.f;
    for (int i = 0; i < RCH; i++) { s += g_psum[i * Cc + c]; sq += g_psq[i * Cc + c]; }
    float mean = s / (float)Mm;
    float var  = sq / (float)Mm - mean * mean;
    float rstd = rsqrtf(var + 1e-5f);
    float a = rstd * gamma[c];
    g_bn_a[c] = a;
    g_bn_b[c] = beta[c] - mean * a;
    float sp = scale_p[c];
    float sc = (sp > 20.f) ? sp : log1pf(expf(sp));
    g_rscale[c] = 1.0f / sc;
}

// ---------------------------------------------------------------------------
// K3: xn = BN(x), split to bf16 hi/lo
// ---------------------------------------------------------------------------
__global__ void prep_x(const float* __restrict__ x) {
    size_t i = (size_t)blockIdx.x * 256 + threadIdx.x;   // float4 index
    float4 v = ((const float4*)x)[i];
    int c = (int)((i * 4) & (Cc - 1));
    v.x = v.x * g_bn_a[c]     + g_bn_b[c];
    v.y = v.y * g_bn_a[c + 1] + g_bn_b[c + 1];
    v.z = v.z * g_bn_a[c + 2] + g_bn_b[c + 2];
    v.w = v.w * g_bn_a[c + 3] + g_bn_b[c + 3];
    __nv_bfloat16 hx = __float2bfloat16(v.x), hy = __float2bfloat16(v.y);
    __nv_bfloat16 hz = __float2bfloat16(v.z), hw = __float2bfloat16(v.w);
    __nv_bfloat162* ph = (__nv_bfloat162*)g_Ahi;
    __nv_bfloat162* pl = (__nv_bfloat162*)g_Alo;
    ph[i * 2]     = {hx, hy};
    ph[i * 2 + 1] = {hz, hw};
    pl[i * 2]     = {__float2bfloat16(v.x - __bfloat162float(hx)),
                     __float2bfloat16(v.y - __bfloat162float(hy))};
    pl[i * 2 + 1] = {__float2bfloat16(v.z - __bfloat162float(hz)),
                     __float2bfloat16(v.w - __bfloat162float(hw))};
}

// ---------------------------------------------------------------------------
// K4: transpose W [K=1024, Nout] -> Wt [Nout, 1024] split to bf16 hi/lo
// ---------------------------------------------------------------------------
__global__ void prep_w(const float* __restrict__ W,
                       __nv_bfloat16* __restrict__ hi, __nv_bfloat16* __restrict__ lo,
                       int Nout) {
    __shared__ float tile[32][33];
    int n0 = blockIdx.x * 32, k0 = blockIdx.y * 32;
    int tx = threadIdx.x, ty = threadIdx.y;     // (32, 8)
#pragma unroll
    for (int j = 0; j < 32; j += 8)
        tile[ty + j][tx] = W[(size_t)(k0 + ty + j) * Nout + n0 + tx];
    __syncthreads();
#pragma unroll
    for (int j = 0; j < 32; j += 8) {
        float v = tile[tx][ty + j];
        size_t oi = (size_t)(n0 + ty + j) * Cc + k0 + tx;
        __nv_bfloat16 h = __float2bfloat16(v);
        hi[oi] = h;
        lo[oi] = __float2bfloat16(v - __bfloat162float(h));
    }
}

// ---------------------------------------------------------------------------
// K5: HMMA GEMM  C[M,Ndim] = A @ Bt^T + bias  (3-term bf16 Markidis)
// BM=128, BN=256, BK=32. 8 warps (2x4), warp tile 64x64.
// cp.async 3-stage pipeline, one __syncthreads per K-iter.
// smem rows padded to 80B (conflict-free ldmatrix).
// ---------------------------------------------------------------------------
#define SROW 80
#define T_AH 0
#define T_AL 10240
#define T_BH 20480
#define T_BL 40960
#define STG  61440
#define NSTAGE 3

__global__ __launch_bounds__(256, 1)
void gemm_mma(const __nv_bfloat16* __restrict__ Ahi, const __nv_bfloat16* __restrict__ Alo,
              const __nv_bfloat16* __restrict__ Bhi, const __nv_bfloat16* __restrict__ Blo,
              const float* __restrict__ bias, float* __restrict__ Cout, int Ndim) {
    extern __shared__ char sm[];
    const int t = threadIdx.x;
    const int wid = t >> 5, lane = t & 31;
    const int m0 = blockIdx.y * 128, n0 = blockIdx.x * 256;
    const int warp_m = wid & 1, warp_n = wid >> 1;   // 2 x 4 warp grid
    const uint32_t sb = smem_u32(sm);

    float acc[4][8][4];
#pragma unroll
    for (int i = 0; i < 4; i++)
#pragma unroll
        for (int j = 0; j < 8; j++)
#pragma unroll
            for (int q = 0; q < 4; q++) acc[i][j][q] = 0.f;

    // per-thread load assignment
    // A tiles: 128 rows x 4 chunks(16B) = 512 chunks -> 2 per thread
    // B tiles: 256 rows x 4 chunks      = 1024 chunks -> 4 per thread
    const int ar0 = t >> 2, ac = t & 3;            // rows 0..63
    const int ar1 = ar0 + 64;                      // rows 64..127
    uint32_t da0 = (uint32_t)ar0 * SROW + ac * 16;
    uint32_t da1 = (uint32_t)ar1 * SROW + ac * 16;

#define LOAD_STAGE(IT)                                                              \
    {                                                                               \
        int k0_ = (IT) * 32;                                                        \
        uint32_t dst = sb + ((IT) % NSTAGE) * STG;                                  \
        cpa16(dst + T_AH + da0, Ahi + (size_t)(m0 + ar0) * Cc + k0_ + ac * 8);      \
        cpa16(dst + T_AH + da1, Ahi + (size_t)(m0 + ar1) * Cc + k0_ + ac * 8);      \
        cpa16(dst + T_AL + da0, Alo + (size_t)(m0 + ar0) * Cc + k0_ + ac * 8);      \
        cpa16(dst + T_AL + da1, Alo + (size_t)(m0 + ar1) * Cc + k0_ + ac * 8);      \
        _Pragma("unroll")                                                           \
        for (int j = 0; j < 4; j++) {                                               \
            int br = ar0 + j * 64;                                                  \
            uint32_t db = (uint32_t)br * SROW + ac * 16;                            \
            cpa16(dst + T_BH + db, Bhi + (size_t)(n0 + br) * Cc + k0_ + ac * 8);    \
            cpa16(dst + T_BL + db, Blo + (size_t)(n0 + br) * Cc + k0_ + ac * 8);    \
        }                                                                           \
        cp_commit();                                                                \
    }

    LOAD_STAGE(0)
    LOAD_STAGE(1)

    // ldmatrix address components (within tiles, 80B row stride)
    const uint32_t a_off = (uint32_t)(warp_m * 64 + (lane & 15)) * SROW + ((lane >> 4) << 3) * 2;
    const uint32_t b_off = (uint32_t)(warp_n * 64 + ((lane & 16) >> 1) + (lane & 7)) * SROW + (lane & 8) * 2;

    for (int it = 0; it < 32; it++) {
        if (it < 31) cp_wait<1>(); else cp_wait<0>();
        __syncthreads();
        // prefetch stage it+2 into buffer consumed at iter it-1 (safe post-barrier)
        if (it + 2 < 32) LOAD_STAGE(it + 2)

        uint32_t base = sb + (it % NSTAGE) * STG;
#pragma unroll
        for (int kk2 = 0; kk2 < 2; kk2++) {
            uint32_t ko = kk2 * 32;   // 16 bf16 = 32 bytes
            uint32_t ah[4][4], al[4][4];
#pragma unroll
            for (int mt = 0; mt < 4; mt++) {
                ldsm4(ah[mt], base + T_AH + a_off + mt * 16 * SROW + ko);
                ldsm4(al[mt], base + T_AL + a_off + mt * 16 * SROW + ko);
            }
#pragma unroll
            for (int nt2 = 0; nt2 < 4; nt2++) {
                uint32_t bhf[4], blf[4];
                ldsm4(bhf, base + T_BH + b_off + nt2 * 16 * SROW + ko);
                ldsm4(blf, base + T_BL + b_off + nt2 * 16 * SROW + ko);
#pragma unroll
                for (int mt = 0; mt < 4; mt++)
#pragma unroll
                    for (int hf = 0; hf < 2; hf++) {
                        int nt = nt2 * 2 + hf;
                        mma16816(acc[mt][nt], ah[mt], &bhf[hf * 2]);
                        mma16816(acc[mt][nt], ah[mt], &blf[hf * 2]);
                        mma16816(acc[mt][nt], al[mt], &bhf[hf * 2]);
                    }
            }
        }
    }

    // epilogue: add bias, store float2 per (mt, nt)
#pragma unroll
    for (int mt = 0; mt < 4; mt++) {
        int row = m0 + warp_m * 64 + mt * 16 + (lane >> 2);
#pragma unroll
        for (int nt = 0; nt < 8; nt++) {
            int col = n0 + warp_n * 64 + nt * 8 + (lane & 3) * 2;
            float b0 = bias[col], b1 = bias[col + 1];
            float2* p0 = (float2*)(Cout + (size_t)row * Ndim + col);
            float2* p1 = (float2*)(Cout + (size_t)(row + 8) * Ndim + col);
            *p0 = {acc[mt][nt][0] + b0, acc[mt][nt][1] + b1};
            *p1 = {acc[mt][nt][2] + b0, acc[mt][nt][3] + b1};
        }
    }
}

// ---------------------------------------------------------------------------
// K6: focused feature map, in place on q / k rows
// ---------------------------------------------------------------------------
__global__ void focus_kernel() {
    int bx  = blockIdx.x;
    int m   = bx >> 1;
    int sel = bx & 1;
    float* p = g_qkv + (size_t)m * C3 + sel * Cc;
    int t = threadIdx.x;

    float t3[4];
    float s2 = 0.f, s6 = 0.f;
#pragma unroll
    for (int i = 0; i < 4; i++) {
        int c = t + i * 256;
        float v = fmaxf(p[c], 0.f) + 1e-6f;
        v = v * g_rscale[c];
        s2 += v * v;
        float v3 = v * v * v;
        t3[i] = v3;
        s6 += v3 * v3;
    }
    __shared__ float sh2[8], sh6[8];
#pragma unroll
    for (int off = 16; off; off >>= 1) {
        s2 += __shfl_xor_sync(0xffffffffu, s2, off);
        s6 += __shfl_xor_sync(0xffffffffu, s6, off);
    }
    int w = t >> 5, lane = t & 31;
    if (lane == 0) { sh2[w] = s2; sh6[w] = s6; }
    __syncthreads();
    if (t == 0) {
        float a = 0.f, b = 0.f;
        for (int i = 0; i < 8; i++) { a += sh2[i]; b += sh6[i]; }
        sh2[0] = a; sh6[0] = b;
    }
    __syncthreads();
    float factor = sqrtf(sh2[0] / sh6[0]);
#pragma unroll
    for (int i = 0; i < 4; i++) p[t + i * 256] = t3[i] * factor;
}

// ---------------------------------------------------------------------------
// K7: per (b,h): kv[d][e] = sum_n k[n,d] v[n,e]; ksum[d] = sum_n k[n,d]
// ---------------------------------------------------------------------------
__global__ __launch_bounds__(256) void kv_kernel() {
    int bh = blockIdx.x;
    int b = bh >> 4, h = bh & 15;
    const float* kbase = g_qkv + (size_t)(b * Nn) * C3 + Cc + h * Dd;
    const float* vbase = kbase + Cc;

    __shared__ float ks[32][65], vs[32][65];
    int t = threadIdx.x;
    int dr = (t >> 4) << 2, ec = (t & 15) << 2;

    float acc[4][4];
#pragma unroll
    for (int i = 0; i < 4; i++)
#pragma unroll
        for (int j = 0; j < 4; j++) acc[i][j] = 0.f;
    float ksacc = 0.f;

    for (int n0 = 0; n0 < Nn; n0 += 32) {
        __syncthreads();
#pragma unroll
        for (int i = 0; i < 8; i++) {
            int idx = t + i * 256;
            int r = idx >> 6, c = idx & 63;
            ks[r][c] = kbase[(size_t)(n0 + r) * C3 + c];
            vs[r][c] = vbase[(size_t)(n0 + r) * C3 + c];
        }
        __syncthreads();
#pragma unroll 8
        for (int n = 0; n < 32; n++) {
            float kd0 = ks[n][dr], kd1 = ks[n][dr + 1], kd2 = ks[n][dr + 2], kd3 = ks[n][dr + 3];
            float v0 = vs[n][ec], v1 = vs[n][ec + 1], v2 = vs[n][ec + 2], v3 = vs[n][ec + 3];
            acc[0][0] += kd0 * v0; acc[0][1] += kd0 * v1; acc[0][2] += kd0 * v2; acc[0][3] += kd0 * v3;
            acc[1][0] += kd1 * v0; acc[1][1] += kd1 * v1; acc[1][2] += kd1 * v2; acc[1][3] += kd1 * v3;
            acc[2][0] += kd2 * v0; acc[2][1] += kd2 * v1; acc[2][2] += kd2 * v2; acc[2][3] += kd2 * v3;
            acc[3][0] += kd3 * v0; acc[3][1] += kd3 * v1; acc[3][2] += kd3 * v2; acc[3][3] += kd3 * v3;
        }
        if (t < 64) {
#pragma unroll 8
            for (int n = 0; n < 32; n++) ksacc += ks[n][t];
        }
    }

    float* kvout = g_kv + bh * (Dd * Dd);
#pragma unroll
    for (int i = 0; i < 4; i++)
#pragma unroll
        for (int j = 0; j < 4; j++)
            kvout[(dr + i) * Dd + ec + j] = acc[i][j];
    if (t < 64) g_ksum[bh * Dd + t] = ksacc;
}

// ---------------------------------------------------------------------------
// K8: o = (q @ kv) * z fused with depthwise conv; writes bf16 hi/lo for proj
// ---------------------------------------------------------------------------
__global__ __launch_bounds__(256) void o_dwc_kernel(const float* __restrict__ dwc_w,
                                                    const float* __restrict__ dwc_b) {
    int bh = blockIdx.x;
    int b = bh >> 4, h = bh & 15;
    int n0 = blockIdx.y * 128;

    __shared__ float kvs[64][65];
    __shared__ float ksums[64];
    __shared__ float qrow[8][64];

    int t = threadIdx.x;
    int w = t >> 5, lane = t & 31;

#pragma unroll
    for (int i = 0; i < 16; i++) {
        int idx = t + i * 256;
        kvs[idx >> 6][idx & 63] = g_kv[bh * (Dd * Dd) + idx];
    }
    if (t < 64) ksums[t] = g_ksum[bh * Dd + t];
    __syncthreads();

    const float* qbase = g_qkv + (size_t)(b * Nn) * C3 + h * Dd;
    const float* vbase = g_qkv + (size_t)(b * Nn) * C3 + 2 * Cc + h * Dd;

    int c0 = h * 64 + lane, c1 = h * 64 + lane + 32;
    float w0[5], w1[5];
#pragma unroll
    for (int j = 0; j < 5; j++) { w0[j] = dwc_w[c0 * 5 + j]; w1[j] = dwc_w[c1 * 5 + j]; }
    float db0 = dwc_b[c0], db1 = dwc_b[c1];

    for (int r = w; r < 128; r += 8) {
        int n = n0 + r;
        const float* qp = qbase + (size_t)n * C3;
        qrow[w][lane]      = qp[lane];
        qrow[w][lane + 32] = qp[lane + 32];
        __syncwarp();

        float s = qrow[w][lane] * ksums[lane] + qrow[w][lane + 32] * ksums[lane + 32];
#pragma unroll
        for (int off = 16; off; off >>= 1) s += __shfl_xor_sync(0xffffffffu, s, off);
        float z = 1.f / (s + 1e-6f);

        float acc0 = 0.f, acc1 = 0.f;
#pragma unroll
        for (int d = 0; d < 64; d++) {
            float qd = qrow[w][d];
            acc0 += qd * kvs[d][lane];
            acc1 += qd * kvs[d][lane + 32];
        }

        float dw0 = db0, dw1 = db1;
#pragma unroll
        for (int j = 0; j < 5; j++) {
            int nn = n + j - 2;
            if ((unsigned)nn < (unsigned)Nn) {
                const float* vp = vbase + (size_t)nn * C3;
                dw0 += vp[lane]      * w0[j];
                dw1 += vp[lane + 32] * w1[j];
            }
        }

        float o0 = acc0 * z + dw0;
        float o1 = acc1 * z + dw1;
        size_t oi = (size_t)(b * Nn + n) * Cc + h * 64;
        __nv_bfloat16 h0 = __float2bfloat16(o0);
        __nv_bfloat16 h1 = __float2bfloat16(o1);
        g_Ohi[oi + lane]      = h0;
        g_Ohi[oi + lane + 32] = h1;
        g_Olo[oi + lane]      = __float2bfloat16(o0 - __bfloat162float(h0));
        g_Olo[oi + lane + 32] = __float2bfloat16(o1 - __bfloat162float(h1));
        __syncwarp();
    }
}

// ---------------------------------------------------------------------------
extern "C" void kernel_launch(void* const* d_in, const int* in_sizes, int n_in,
                              void* d_out, int out_size) {
    const float* x       = (const float*)d_in[0];
    const float* gamma   = (const float*)d_in[1];
    const float* beta    = (const float*)d_in[2];
    const float* Wqkv    = (const float*)d_in[3];
    const float* bqkv    = (const float*)d_in[4];
    const float* scale_p = (const float*)d_in[5];
    const float* dwc_w   = (const float*)d_in[6];
    const float* dwc_b   = (const float*)d_in[7];
    const float* Wproj   = (const float*)d_in[8];
    const float* bproj   = (const float*)d_in[9];
    float* out = (float*)d_out;

    void *p_qkv, *p_Ahi, *p_Alo, *p_Ohi, *p_Olo, *p_Wqh, *p_Wql, *p_Wph, *p_Wpl;
    cudaGetSymbolAddress(&p_qkv, g_qkv);
    cudaGetSymbolAddress(&p_Ahi, g_Ahi);
    cudaGetSymbolAddress(&p_Alo, g_Alo);
    cudaGetSymbolAddress(&p_Ohi, g_Ohi);
    cudaGetSymbolAddress(&p_Olo, g_Olo);
    cudaGetSymbolAddress(&p_Wqh, g_Wqh);
    cudaGetSymbolAddress(&p_Wql, g_Wql);
    cudaGetSymbolAddress(&p_Wph, g_Wph);
    cudaGetSymbolAddress(&p_Wpl, g_Wpl);

    const int SMEM_GEMM = NSTAGE * STG;   // 184320 bytes
    static int attr_done = 0;
    if (!attr_done) {
        cudaFuncSetAttribute(gemm_mma, cudaFuncAttributeMaxDynamicSharedMemorySize, SMEM_GEMM);
        attr_done = 1;
    }

    // 1. BN stats
    bn_partial<<<dim3(8, RCH), 128>>>(x);
    bn_finalize<<<4, 256>>>(gamma, beta, scale_p);

    // 2. operand prep: BN(x) -> bf16 hi/lo; transpose+split weights
    prep_x<<<(Mm * Cc / 4) / 256, 256>>>(x);
    prep_w<<<dim3(C3 / 32, Cc / 32), dim3(32, 8)>>>(Wqkv, (__nv_bfloat16*)p_Wqh, (__nv_bfloat16*)p_Wql, C3);
    prep_w<<<dim3(Cc / 32, Cc / 32), dim3(32, 8)>>>(Wproj, (__nv_bfloat16*)p_Wph, (__nv_bfloat16*)p_Wpl, Cc);

    // 3. QKV GEMM (HMMA): [16384,1024] @ [1024,3072] + bias
    gemm_mma<<<dim3(C3 / 256, Mm / 128), 256, SMEM_GEMM>>>(
        (const __nv_bfloat16*)p_Ahi, (const __nv_bfloat16*)p_Alo,
        (const __nv_bfloat16*)p_Wqh, (const __nv_bfloat16*)p_Wql,
        bqkv, (float*)p_qkv, C3);

    // 4. focus(q), focus(k) in place
    focus_kernel<<<2 * Mm, 256>>>();

    // 5. per-(b,h) K^T V and k-sum
    kv_kernel<<<Bb * Hh, 256>>>();

    // 6. o = (q @ kv) * z + dwc residual -> bf16 hi/lo
    o_dwc_kernel<<<dim3(Bb * Hh, Nn / 128), 256>>>(dwc_w, dwc_b);

    // 7. proj GEMM (HMMA): [16384,1024] @ [1024,1024] + bias -> out
    gemm_mma<<<dim3(Cc / 256, Mm / 128), 256, SMEM_GEMM>>>(
        (const __nv_bfloat16*)p_Ohi, (const __nv_bfloat16*)p_Olo,
        (const __nv_bfloat16*)p_Wph, (const __nv_bfloat16*)p_Wpl,
        bproj, out, Cc);
}

// round 9
// speedup vs baseline: 2.3425x; 1.1080x over previous
#include <cuda_runtime.h>
#include <cuda_bf16.h>
#include <cuda_fp16.h>
#include <math.h>
#include <stdint.h>

#define Bb 8
#define Nn 2048
#define Cc 1024
#define Hh 16
#define Dd 64
#define Mm (Bb*Nn)      /* 16384 */
#define C3 (3*Cc)       /* 3072  */
#define RCH 64

// ---- scratch (static device globals; no allocations allowed) ----
__device__ float g_qkv[(size_t)Mm*C3];     // q|k|v per row (f32)
__device__ float g_kv[Bb*Hh*Dd*Dd];
__device__ float g_ksum[Bb*Hh*Dd];
__device__ float g_bn_a[Cc], g_bn_b[Cc], g_rscale[Cc];
__device__ float g_psum[RCH*Cc], g_psq[RCH*Cc];
// bf16 hi/lo split of BN(x) for qk 3-term GEMM
__device__ __nv_bfloat16 g_Ahi[(size_t)Mm*Cc], g_Alo[(size_t)Mm*Cc];
// fp16 hi/lo split of BN(x) for v 2-term GEMM
__device__ __half g_Ah16[(size_t)Mm*Cc], g_Al16[(size_t)Mm*Cc];
// fp16 hi/lo of (o + dwc) for proj 2-term GEMM
__device__ __half g_Oh16[(size_t)Mm*Cc], g_Ol16[(size_t)Mm*Cc];
// weights: qk part bf16 hi/lo (transposed, rows = out-cols 0..2047)
__device__ __nv_bfloat16 g_Wqh[(size_t)2048*Cc], g_Wql[(size_t)2048*Cc];
// weights: v part + proj, fp16 hi only (transposed)
__device__ __half g_Wvh[(size_t)Cc*Cc], g_Wph16[(size_t)Cc*Cc];

// ---------------------------------------------------------------------------
// helpers
// ---------------------------------------------------------------------------
__device__ __forceinline__ uint32_t smem_u32(const void* p) {
    uint32_t a;
    asm("{ .reg .u64 t; cvta.to.shared.u64 t, %1; cvt.u32.u64 %0, t; }"
        : "=r"(a) : "l"(p));
    return a;
}
__device__ __forceinline__ void cpa16(uint32_t dst, const void* src) {
    asm volatile("cp.async.cg.shared.global [%0], [%1], 16;" :: "r"(dst), "l"(src));
}
__device__ __forceinline__ void cp_commit() {
    asm volatile("cp.async.commit_group;" ::: "memory");
}
template <int N>
__device__ __forceinline__ void cp_wait() {
    asm volatile("cp.async.wait_group %0;" :: "n"(N) : "memory");
}
__device__ __forceinline__ void ldsm4(uint32_t* r, uint32_t addr) {
    asm volatile("ldmatrix.sync.aligned.m8n8.x4.shared.b16 {%0,%1,%2,%3}, [%4];"
                 : "=r"(r[0]), "=r"(r[1]), "=r"(r[2]), "=r"(r[3]) : "r"(addr));
}
__device__ __forceinline__ void mma_bf(float* d, const uint32_t* a, const uint32_t* b) {
    asm volatile(
        "mma.sync.aligned.m16n8k16.row.col.f32.bf16.bf16.f32 "
        "{%0,%1,%2,%3}, {%4,%5,%6,%7}, {%8,%9}, {%0,%1,%2,%3};"
        : "+f"(d[0]), "+f"(d[1]), "+f"(d[2]), "+f"(d[3])
        : "r"(a[0]), "r"(a[1]), "r"(a[2]), "r"(a[3]), "r"(b[0]), "r"(b[1]));
}
__device__ __forceinline__ void mma_fp(float* d, const uint32_t* a, const uint32_t* b) {
    asm volatile(
        "mma.sync.aligned.m16n8k16.row.col.f32.f16.f16.f32 "
        "{%0,%1,%2,%3}, {%4,%5,%6,%7}, {%8,%9}, {%0,%1,%2,%3};"
        : "+f"(d[0]), "+f"(d[1]), "+f"(d[2]), "+f"(d[3])
        : "r"(a[0]), "r"(a[1]), "r"(a[2]), "r"(a[3]), "r"(b[0]), "r"(b[1]));
}

// ---------------------------------------------------------------------------
// K1: per-channel partial sums (deterministic, no atomics)
// ---------------------------------------------------------------------------
__global__ void bn_partial(const float* __restrict__ x) {
    int c = blockIdx.x * 128 + threadIdx.x;
    int chunk = blockIdx.y;
    const int RPC = Mm / RCH;
    const float* p = x + (size_t)(chunk * RPC) * Cc + c;
    float s = 0.f, sq = 0.f;
    for (int r = 0; r < RPC; r++) { float v = p[(size_t)r * Cc]; s += v; sq += v * v; }
    g_psum[chunk * Cc + c] = s;
    g_psq[chunk * Cc + c]  = sq;
}

// ---------------------------------------------------------------------------
// K2: finalize BN affine + reciprocal softplus(scale_p)
// ---------------------------------------------------------------------------
__global__ void bn_finalize(const float* __restrict__ gamma,
                            const float* __restrict__ beta,
                            const float* __restrict__ scale_p) {
    int c = blockIdx.x * 256 + threadIdx.x;
    float s = 0.f, sq = 0.f;
    for (int i = 0; i < RCH; i++) { s += g_psum[i * Cc + c]; sq += g_psq[i * Cc + c]; }
    float mean = s / (float)Mm;
    float var  = sq / (float)Mm - mean * mean;
    float rstd = rsqrtf(var + 1e-5f);
    float a = rstd * gamma[c];
    g_bn_a[c] = a;
    g_bn_b[c] = beta[c] - mean * a;
    float sp = scale_p[c];
    float sc = (sp > 20.f) ? sp : log1pf(expf(sp));
    g_rscale[c] = 1.0f / sc;
}

// ---------------------------------------------------------------------------
// K3: xn = BN(x) -> bf16 hi/lo AND fp16 hi/lo
// ---------------------------------------------------------------------------
__global__ void prep_x(const float* __restrict__ x) {
    size_t i = (size_t)blockIdx.x * 256 + threadIdx.x;   // float4 index
    float4 v = ((const float4*)x)[i];
    int c = (int)((i * 4) & (Cc - 1));
    float f[4];
    f[0] = v.x * g_bn_a[c]     + g_bn_b[c];
    f[1] = v.y * g_bn_a[c + 1] + g_bn_b[c + 1];
    f[2] = v.z * g_bn_a[c + 2] + g_bn_b[c + 2];
    f[3] = v.w * g_bn_a[c + 3] + g_bn_b[c + 3];

    __nv_bfloat162* ph = (__nv_bfloat162*)g_Ahi;
    __nv_bfloat162* pl = (__nv_bfloat162*)g_Alo;
    __nv_bfloat16 bh[4], bl[4];
#pragma unroll
    for (int j = 0; j < 4; j++) {
        bh[j] = __float2bfloat16(f[j]);
        bl[j] = __float2bfloat16(f[j] - __bfloat162float(bh[j]));
    }
    ph[i * 2]     = {bh[0], bh[1]};
    ph[i * 2 + 1] = {bh[2], bh[3]};
    pl[i * 2]     = {bl[0], bl[1]};
    pl[i * 2 + 1] = {bl[2], bl[3]};

    __half2* qh = (__half2*)g_Ah16;
    __half2* ql = (__half2*)g_Al16;
    __half hh[4], hl[4];
#pragma unroll
    for (int j = 0; j < 4; j++) {
        hh[j] = __float2half(f[j]);
        hl[j] = __float2half(f[j] - __half2float(hh[j]));
    }
    qh[i * 2]     = {hh[0], hh[1]};
    qh[i * 2 + 1] = {hh[2], hh[3]};
    ql[i * 2]     = {hl[0], hl[1]};
    ql[i * 2 + 1] = {hl[2], hl[3]};
}

// ---------------------------------------------------------------------------
// K4a: transpose W [K=1024, Nout] cols [0,2048) -> bf16 hi/lo rows
// ---------------------------------------------------------------------------
__global__ void prep_w_bf(const float* __restrict__ W,
                          __nv_bfloat16* __restrict__ hi, __nv_bfloat16* __restrict__ lo,
                          int Nout) {
    __shared__ float tile[32][33];
    int n0 = blockIdx.x * 32, k0 = blockIdx.y * 32;
    int tx = threadIdx.x, ty = threadIdx.y;     // (32, 8)
#pragma unroll
    for (int j = 0; j < 32; j += 8)
        tile[ty + j][tx] = W[(size_t)(k0 + ty + j) * Nout + n0 + tx];
    __syncthreads();
#pragma unroll
    for (int j = 0; j < 32; j += 8) {
        float v = tile[tx][ty + j];
        size_t oi = (size_t)(n0 + ty + j) * Cc + k0 + tx;
        __nv_bfloat16 h = __float2bfloat16(v);
        hi[oi] = h;
        lo[oi] = __float2bfloat16(v - __bfloat162float(h));
    }
}

// ---------------------------------------------------------------------------
// K4b: transpose W [K=1024, Nout] cols [nbase, nbase+1024) -> fp16 hi rows
// ---------------------------------------------------------------------------
__global__ void prep_w_fp(const float* __restrict__ W,
                          __half* __restrict__ hi, int Nout, int nbase) {
    __shared__ float tile[32][33];
    int n0 = nbase + blockIdx.x * 32, k0 = blockIdx.y * 32;
    int tx = threadIdx.x, ty = threadIdx.y;     // (32, 8)
#pragma unroll
    for (int j = 0; j < 32; j += 8)
        tile[ty + j][tx] = W[(size_t)(k0 + ty + j) * Nout + n0 + tx];
    __syncthreads();
#pragma unroll
    for (int j = 0; j < 32; j += 8) {
        float v = tile[tx][ty + j];
        size_t oi = (size_t)(n0 - nbase + ty + j) * Cc + k0 + tx;
        hi[oi] = __float2half(v);
    }
}

// ---------------------------------------------------------------------------
// K5: bf16 3-term HMMA GEMM (AhiBhi + AhiBlo + AloBhi)
// BM=128, BN=256, BK=32. 8 warps (2x4), warp tile 64x64. 3-stage cp.async.
// ---------------------------------------------------------------------------
#define SROW 80
#define T_AH 0
#define T_AL 10240
#define T_BH 20480
#define T_BL 40960
#define STG3 61440
#define NST3 3

__global__ __launch_bounds__(256, 1)
void gemm3_bf(const __nv_bfloat16* __restrict__ Ahi, const __nv_bfloat16* __restrict__ Alo,
              const __nv_bfloat16* __restrict__ Bhi, const __nv_bfloat16* __restrict__ Blo,
              const float* __restrict__ bias, float* __restrict__ Cout, int Ndim) {
    extern __shared__ char sm[];
    const int t = threadIdx.x;
    const int wid = t >> 5, lane = t & 31;
    const int m0 = blockIdx.y * 128, n0 = blockIdx.x * 256;
    const int warp_m = wid & 1, warp_n = wid >> 1;   // 2 x 4 warp grid
    const uint32_t sb = smem_u32(sm);

    float acc[4][8][4];
#pragma unroll
    for (int i = 0; i < 4; i++)
#pragma unroll
        for (int j = 0; j < 8; j++)
#pragma unroll
            for (int q = 0; q < 4; q++) acc[i][j][q] = 0.f;

    const int ar0 = t >> 2, ac = t & 3;
    const int ar1 = ar0 + 64;
    uint32_t da0 = (uint32_t)ar0 * SROW + ac * 16;
    uint32_t da1 = (uint32_t)ar1 * SROW + ac * 16;

#define LOAD3(IT)                                                                   \
    {                                                                               \
        int k0_ = (IT) * 32;                                                        \
        uint32_t dst = sb + ((IT) % NST3) * STG3;                                   \
        cpa16(dst + T_AH + da0, Ahi + (size_t)(m0 + ar0) * Cc + k0_ + ac * 8);      \
        cpa16(dst + T_AH + da1, Ahi + (size_t)(m0 + ar1) * Cc + k0_ + ac * 8);      \
        cpa16(dst + T_AL + da0, Alo + (size_t)(m0 + ar0) * Cc + k0_ + ac * 8);      \
        cpa16(dst + T_AL + da1, Alo + (size_t)(m0 + ar1) * Cc + k0_ + ac * 8);      \
        _Pragma("unroll")                                                           \
        for (int j = 0; j < 4; j++) {                                               \
            int br = ar0 + j * 64;                                                  \
            uint32_t db = (uint32_t)br * SROW + ac * 16;                            \
            cpa16(dst + T_BH + db, Bhi + (size_t)(n0 + br) * Cc + k0_ + ac * 8);    \
            cpa16(dst + T_BL + db, Blo + (size_t)(n0 + br) * Cc + k0_ + ac * 8);    \
        }                                                                           \
        cp_commit();                                                                \
    }

    LOAD3(0)
    LOAD3(1)

    const uint32_t a_off = (uint32_t)(warp_m * 64 + (lane & 15)) * SROW + ((lane >> 4) << 3) * 2;
    const uint32_t b_off = (uint32_t)(warp_n * 64 + ((lane & 16) >> 1) + (lane & 7)) * SROW + (lane & 8) * 2;

    for (int it = 0; it < 32; it++) {
        if (it < 31) cp_wait<1>(); else cp_wait<0>();
        __syncthreads();
        if (it + 2 < 32) LOAD3(it + 2)

        uint32_t base = sb + (it % NST3) * STG3;
#pragma unroll
        for (int kk2 = 0; kk2 < 2; kk2++) {
            uint32_t ko = kk2 * 32;
            uint32_t ah[4][4], al[4][4];
#pragma unroll
            for (int mt = 0; mt < 4; mt++) {
                ldsm4(ah[mt], base + T_AH + a_off + mt * 16 * SROW + ko);
                ldsm4(al[mt], base + T_AL + a_off + mt * 16 * SROW + ko);
            }
#pragma unroll
            for (int nt2 = 0; nt2 < 4; nt2++) {
                uint32_t bhf[4], blf[4];
                ldsm4(bhf, base + T_BH + b_off + nt2 * 16 * SROW + ko);
                ldsm4(blf, base + T_BL + b_off + nt2 * 16 * SROW + ko);
#pragma unroll
                for (int mt = 0; mt < 4; mt++)
#pragma unroll
                    for (int hf = 0; hf < 2; hf++) {
                        int nt = nt2 * 2 + hf;
                        mma_bf(acc[mt][nt], ah[mt], &bhf[hf * 2]);
                        mma_bf(acc[mt][nt], ah[mt], &blf[hf * 2]);
                        mma_bf(acc[mt][nt], al[mt], &bhf[hf * 2]);
                    }
            }
        }
    }

#pragma unroll
    for (int mt = 0; mt < 4; mt++) {
        int row = m0 + warp_m * 64 + mt * 16 + (lane >> 2);
#pragma unroll
        for (int nt = 0; nt < 8; nt++) {
            int col = n0 + warp_n * 64 + nt * 8 + (lane & 3) * 2;
            float b0 = bias[col], b1 = bias[col + 1];
            float2* p0 = (float2*)(Cout + (size_t)row * Ndim + col);
            float2* p1 = (float2*)(Cout + (size_t)(row + 8) * Ndim + col);
            *p0 = {acc[mt][nt][0] + b0, acc[mt][nt][1] + b1};
            *p1 = {acc[mt][nt][2] + b0, acc[mt][nt][3] + b1};
        }
    }
}

// ---------------------------------------------------------------------------
// K5b: fp16 2-term HMMA GEMM (AhiBhi + AloBhi), B single fp16
// Same tiling; stage = Ahi|Alo|Bhi = 40960 B, 3 stages.
// ---------------------------------------------------------------------------
#define STG2 40960
#define NST2 3

__global__ __launch_bounds__(256, 1)
void gemm2_fp(const __half* __restrict__ Ahi, const __half* __restrict__ Alo,
              const __half* __restrict__ Bhi,
              const float* __restrict__ bias, float* __restrict__ Cout, int Ndim) {
    extern __shared__ char sm[];
    const int t = threadIdx.x;
    const int wid = t >> 5, lane = t & 31;
    const int m0 = blockIdx.y * 128, n0 = blockIdx.x * 256;
    const int warp_m = wid & 1, warp_n = wid >> 1;
    const uint32_t sb = smem_u32(sm);

    float acc[4][8][4];
#pragma unroll
    for (int i = 0; i < 4; i++)
#pragma unroll
        for (int j = 0; j < 8; j++)
#pragma unroll
            for (int q = 0; q < 4; q++) acc[i][j][q] = 0.f;

    const int ar0 = t >> 2, ac = t & 3;
    const int ar1 = ar0 + 64;
    uint32_t da0 = (uint32_t)ar0 * SROW + ac * 16;
    uint32_t da1 = (uint32_t)ar1 * SROW + ac * 16;

#define LOAD2(IT)                                                                   \
    {                                                                               \
        int k0_ = (IT) * 32;                                                        \
        uint32_t dst = sb + ((IT) % NST2) * STG2;                                   \
        cpa16(dst + T_AH + da0, Ahi + (size_t)(m0 + ar0) * Cc + k0_ + ac * 8);      \
        cpa16(dst + T_AH + da1, Ahi + (size_t)(m0 + ar1) * Cc + k0_ + ac * 8);      \
        cpa16(dst + T_AL + da0, Alo + (size_t)(m0 + ar0) * Cc + k0_ + ac * 8);      \
        cpa16(dst + T_AL + da1, Alo + (size_t)(m0 + ar1) * Cc + k0_ + ac * 8);      \
        _Pragma("unroll")                                                           \
        for (int j = 0; j < 4; j++) {                                               \
            int br = ar0 + j * 64;                                                  \
            uint32_t db = (uint32_t)br * SROW + ac * 16;                            \
            cpa16(dst + T_BH + db, Bhi + (size_t)(n0 + br) * Cc + k0_ + ac * 8);    \
        }                                                                           \
        cp_commit();                                                                \
    }

    LOAD2(0)
    LOAD2(1)

    const uint32_t a_off = (uint32_t)(warp_m * 64 + (lane & 15)) * SROW + ((lane >> 4) << 3) * 2;
    const uint32_t b_off = (uint32_t)(warp_n * 64 + ((lane & 16) >> 1) + (lane & 7)) * SROW + (lane & 8) * 2;

    for (int it = 0; it < 32; it++) {
        if (it < 31) cp_wait<1>(); else cp_wait<0>();
        __syncthreads();
        if (it + 2 < 32) LOAD2(it + 2)

        uint32_t base = sb + (it % NST2) * STG2;
#pragma unroll
        for (int kk2 = 0; kk2 < 2; kk2++) {
            uint32_t ko = kk2 * 32;
            uint32_t ah[4][4], al[4][4];
#pragma unroll
            for (int mt = 0; mt < 4; mt++) {
                ldsm4(ah[mt], base + T_AH + a_off + mt * 16 * SROW + ko);
                ldsm4(al[mt], base + T_AL + a_off + mt * 16 * SROW + ko);
            }
#pragma unroll
            for (int nt2 = 0; nt2 < 4; nt2++) {
                uint32_t bhf[4];
                ldsm4(bhf, base + T_BH + b_off + nt2 * 16 * SROW + ko);
#pragma unroll
                for (int mt = 0; mt < 4; mt++)
#pragma unroll
                    for (int hf = 0; hf < 2; hf++) {
                        int nt = nt2 * 2 + hf;
                        mma_fp(acc[mt][nt], ah[mt], &bhf[hf * 2]);
                        mma_fp(acc[mt][nt], al[mt], &bhf[hf * 2]);
                    }
            }
        }
    }

#pragma unroll
    for (int mt = 0; mt < 4; mt++) {
        int row = m0 + warp_m * 64 + mt * 16 + (lane >> 2);
#pragma unroll
        for (int nt = 0; nt < 8; nt++) {
            int col = n0 + warp_n * 64 + nt * 8 + (lane & 3) * 2;
            float b0 = bias[col], b1 = bias[col + 1];
            float2* p0 = (float2*)(Cout + (size_t)row * Ndim + col);
            float2* p1 = (float2*)(Cout + (size_t)(row + 8) * Ndim + col);
            *p0 = {acc[mt][nt][0] + b0, acc[mt][nt][1] + b1};
            *p1 = {acc[mt][nt][2] + b0, acc[mt][nt][3] + b1};
        }
    }
}

// ---------------------------------------------------------------------------
// K6: focused feature map, in place on q / k rows
// ---------------------------------------------------------------------------
__global__ void focus_kernel() {
    int bx  = blockIdx.x;
    int m   = bx >> 1;
    int sel = bx & 1;
    float* p = g_qkv + (size_t)m * C3 + sel * Cc;
    int t = threadIdx.x;

    float t3[4];
    float s2 = 0.f, s6 = 0.f;
#pragma unroll
    for (int i = 0; i < 4; i++) {
        int c = t + i * 256;
        float v = fmaxf(p[c], 0.f) + 1e-6f;
        v = v * g_rscale[c];
        s2 += v * v;
        float v3 = v * v * v;
        t3[i] = v3;
        s6 += v3 * v3;
    }
    __shared__ float sh2[8], sh6[8];
#pragma unroll
    for (int off = 16; off; off >>= 1) {
        s2 += __shfl_xor_sync(0xffffffffu, s2, off);
        s6 += __shfl_xor_sync(0xffffffffu, s6, off);
    }
    int w = t >> 5, lane = t & 31;
    if (lane == 0) { sh2[w] = s2; sh6[w] = s6; }
    __syncthreads();
    if (t == 0) {
        float a = 0.f, b = 0.f;
        for (int i = 0; i < 8; i++) { a += sh2[i]; b += sh6[i]; }
        sh2[0] = a; sh6[0] = b;
    }
    __syncthreads();
    float factor = sqrtf(sh2[0] / sh6[0]);
#pragma unroll
    for (int i = 0; i < 4; i++) p[t + i * 256] = t3[i] * factor;
}

// ---------------------------------------------------------------------------
// K7: per (b,h): kv[d][e] = sum_n k[n,d] v[n,e]; ksum[d] = sum_n k[n,d]
// ---------------------------------------------------------------------------
__global__ __launch_bounds__(256) void kv_kernel() {
    int bh = blockIdx.x;
    int b = bh >> 4, h = bh & 15;
    const float* kbase = g_qkv + (size_t)(b * Nn) * C3 + Cc + h * Dd;
    const float* vbase = kbase + Cc;

    __shared__ float ks[32][65], vs[32][65];
    int t = threadIdx.x;
    int dr = (t >> 4) << 2, ec = (t & 15) << 2;

    float acc[4][4];
#pragma unroll
    for (int i = 0; i < 4; i++)
#pragma unroll
        for (int j = 0; j < 4; j++) acc[i][j] = 0.f;
    float ksacc = 0.f;

    for (int n0 = 0; n0 < Nn; n0 += 32) {
        __syncthreads();
#pragma unroll
        for (int i = 0; i < 8; i++) {
            int idx = t + i * 256;
            int r = idx >> 6, c = idx & 63;
            ks[r][c] = kbase[(size_t)(n0 + r) * C3 + c];
            vs[r][c] = vbase[(size_t)(n0 + r) * C3 + c];
        }
        __syncthreads();
#pragma unroll 8
        for (int n = 0; n < 32; n++) {
            float kd0 = ks[n][dr], kd1 = ks[n][dr + 1], kd2 = ks[n][dr + 2], kd3 = ks[n][dr + 3];
            float v0 = vs[n][ec], v1 = vs[n][ec + 1], v2 = vs[n][ec + 2], v3 = vs[n][ec + 3];
            acc[0][0] += kd0 * v0; acc[0][1] += kd0 * v1; acc[0][2] += kd0 * v2; acc[0][3] += kd0 * v3;
            acc[1][0] += kd1 * v0; acc[1][1] += kd1 * v1; acc[1][2] += kd1 * v2; acc[1][3] += kd1 * v3;
            acc[2][0] += kd2 * v0; acc[2][1] += kd2 * v1; acc[2][2] += kd2 * v2; acc[2][3] += kd2 * v3;
            acc[3][0] += kd3 * v0; acc[3][1] += kd3 * v1; acc[3][2] += kd3 * v2; acc[3][3] += kd3 * v3;
        }
        if (t < 64) {
#pragma unroll 8
            for (int n = 0; n < 32; n++) ksacc += ks[n][t];
        }
    }

    float* kvout = g_kv + bh * (Dd * Dd);
#pragma unroll
    for (int i = 0; i < 4; i++)
#pragma unroll
        for (int j = 0; j < 4; j++)
            kvout[(dr + i) * Dd + ec + j] = acc[i][j];
    if (t < 64) g_ksum[bh * Dd + t] = ksacc;
}

// ---------------------------------------------------------------------------
// K8: o = (q @ kv) * z fused with depthwise conv; writes fp16 hi/lo for proj
// ---------------------------------------------------------------------------
__global__ __launch_bounds__(256) void o_dwc_kernel(const float* __restrict__ dwc_w,
                                                    const float* __restrict__ dwc_b) {
    int bh = blockIdx.x;
    int b = bh >> 4, h = bh & 15;
    int n0 = blockIdx.y * 128;

    __shared__ float kvs[64][65];
    __shared__ float ksums[64];
    __shared__ float qrow[8][64];

    int t = threadIdx.x;
    int w = t >> 5, lane = t & 31;

#pragma unroll
    for (int i = 0; i < 16; i++) {
        int idx = t + i * 256;
        kvs[idx >> 6][idx & 63] = g_kv[bh * (Dd * Dd) + idx];
    }
    if (t < 64) ksums[t] = g_ksum[bh * Dd + t];
    __syncthreads();

    const float* qbase = g_qkv + (size_t)(b * Nn) * C3 + h * Dd;
    const float* vbase = g_qkv + (size_t)(b * Nn) * C3 + 2 * Cc + h * Dd;

    int c0 = h * 64 + lane, c1 = h * 64 + lane + 32;
    float w0[5], w1[5];
#pragma unroll
    for (int j = 0; j < 5; j++) { w0[j] = dwc_w[c0 * 5 + j]; w1[j] = dwc_w[c1 * 5 + j]; }
    float db0 = dwc_b[c0], db1 = dwc_b[c1];

    for (int r = w; r < 128; r += 8) {
        int n = n0 + r;
        const float* qp = qbase + (size_t)n * C3;
        qrow[w][lane]      = qp[lane];
        qrow[w][lane + 32] = qp[lane + 32];
        __syncwarp();

        float s = qrow[w][lane] * ksums[lane] + qrow[w][lane + 32] * ksums[lane + 32];
#pragma unroll
        for (int off = 16; off; off >>= 1) s += __shfl_xor_sync(0xffffffffu, s, off);
        float z = 1.f / (s + 1e-6f);

        float acc0 = 0.f, acc1 = 0.f;
#pragma unroll
        for (int d = 0; d < 64; d++) {
            float qd = qrow[w][d];
            acc0 += qd * kvs[d][lane];
            acc1 += qd * kvs[d][lane + 32];
        }

        float dw0 = db0, dw1 = db1;
#pragma unroll
        for (int j = 0; j < 5; j++) {
            int nn = n + j - 2;
            if ((unsigned)nn < (unsigned)Nn) {
                const float* vp = vbase + (size_t)nn * C3;
                dw0 += vp[lane]      * w0[j];
                dw1 += vp[lane + 32] * w1[j];
            }
        }

        float o0 = acc0 * z + dw0;
        float o1 = acc1 * z + dw1;
        size_t oi = (size_t)(b * Nn + n) * Cc + h * 64;
        __half h0 = __float2half(o0);
        __half h1 = __float2half(o1);
        g_Oh16[oi + lane]      = h0;
        g_Oh16[oi + lane + 32] = h1;
        g_Ol16[oi + lane]      = __float2half(o0 - __half2float(h0));
        g_Ol16[oi + lane + 32] = __float2half(o1 - __half2float(h1));
        __syncwarp();
    }
}

// ---------------------------------------------------------------------------
extern "C" void kernel_launch(void* const* d_in, const int* in_sizes, int n_in,
                              void* d_out, int out_size) {
    const float* x       = (const float*)d_in[0];
    const float* gamma   = (const float*)d_in[1];
    const float* beta    = (const float*)d_in[2];
    const float* Wqkv    = (const float*)d_in[3];
    const float* bqkv    = (const float*)d_in[4];
    const float* scale_p = (const float*)d_in[5];
    const float* dwc_w   = (const float*)d_in[6];
    const float* dwc_b   = (const float*)d_in[7];
    const float* Wproj   = (const float*)d_in[8];
    const float* bproj   = (const float*)d_in[9];
    float* out = (float*)d_out;

    void *p_qkv, *p_Ahi, *p_Alo, *p_Ah16, *p_Al16, *p_Oh16, *p_Ol16;
    void *p_Wqh, *p_Wql, *p_Wvh, *p_Wph16;
    cudaGetSymbolAddress(&p_qkv, g_qkv);
    cudaGetSymbolAddress(&p_Ahi, g_Ahi);
    cudaGetSymbolAddress(&p_Alo, g_Alo);
    cudaGetSymbolAddress(&p_Ah16, g_Ah16);
    cudaGetSymbolAddress(&p_Al16, g_Al16);
    cudaGetSymbolAddress(&p_Oh16, g_Oh16);
    cudaGetSymbolAddress(&p_Ol16, g_Ol16);
    cudaGetSymbolAddress(&p_Wqh, g_Wqh);
    cudaGetSymbolAddress(&p_Wql, g_Wql);
    cudaGetSymbolAddress(&p_Wvh, g_Wvh);
    cudaGetSymbolAddress(&p_Wph16, g_Wph16);

    static int attr_done = 0;
    if (!attr_done) {
        cudaFuncSetAttribute(gemm3_bf, cudaFuncAttributeMaxDynamicSharedMemorySize, NST3 * STG3);
        cudaFuncSetAttribute(gemm2_fp, cudaFuncAttributeMaxDynamicSharedMemorySize, NST2 * STG2);
        attr_done = 1;
    }

    // 1. BN stats
    bn_partial<<<dim3(8, RCH), 128>>>(x);
    bn_finalize<<<4, 256>>>(gamma, beta, scale_p);

    // 2. operand prep
    prep_x<<<(Mm * Cc / 4) / 256, 256>>>(x);
    prep_w_bf<<<dim3(64, 32), dim3(32, 8)>>>(Wqkv, (__nv_bfloat16*)p_Wqh, (__nv_bfloat16*)p_Wql, C3);
    prep_w_fp<<<dim3(32, 32), dim3(32, 8)>>>(Wqkv, (__half*)p_Wvh, C3, 2048);
    prep_w_fp<<<dim3(32, 32), dim3(32, 8)>>>(Wproj, (__half*)p_Wph16, Cc, 0);

    // 3a. qk GEMM (bf16 3-term): [16384,1024]@[1024,2048]
    gemm3_bf<<<dim3(2048 / 256, Mm / 128), 256, NST3 * STG3>>>(
        (const __nv_bfloat16*)p_Ahi, (const __nv_bfloat16*)p_Alo,
        (const __nv_bfloat16*)p_Wqh, (const __nv_bfloat16*)p_Wql,
        bqkv, (float*)p_qkv, C3);

    // 3b. v GEMM (fp16 2-term): [16384,1024]@[1024,1024] -> qkv cols [2048,3072)
    gemm2_fp<<<dim3(Cc / 256, Mm / 128), 256, NST2 * STG2>>>(
        (const __half*)p_Ah16, (const __half*)p_Al16, (const __half*)p_Wvh,
        bqkv + 2048, (float*)p_qkv + 2048, C3);

    // 4. focus(q), focus(k) in place
    focus_kernel<<<2 * Mm, 256>>>();

    // 5. per-(b,h) K^T V and k-sum
    kv_kernel<<<Bb * Hh, 256>>>();

    // 6. o = (q @ kv) * z + dwc residual -> fp16 hi/lo
    o_dwc_kernel<<<dim3(Bb * Hh, Nn / 128), 256>>>(dwc_w, dwc_b);

    // 7. proj GEMM (fp16 2-term): [16384,1024]@[1024,1024] + bias -> out
    gemm2_fp<<<dim3(Cc / 256, Mm / 128), 256, NST2 * STG2>>>(
        (const __half*)p_Oh16, (const __half*)p_Ol16, (const __half*)p_Wph16,
        bproj, out, Cc);
}

// round 15
// speedup vs baseline: 2.6245x; 1.1204x over previous
#include <cuda_runtime.h>
#include <cuda_bf16.h>
#include <cuda_fp16.h>
#include <math.h>
#include <stdint.h>

#define Bb 8
#define Nn 2048
#define Cc 1024
#define Hh 16
#define Dd 64
#define Mm (Bb*Nn)      /* 16384 */
#define C3 (3*Cc)       /* 3072  */
#define RCH 64

// ---- scratch (static device globals; no allocations allowed) ----
__device__ float g_qkv[(size_t)Mm*C3];     // q|k|v per row (f32)
__device__ float g_kv[Bb*Hh*Dd*Dd];
__device__ float g_ksum[Bb*Hh*Dd];
__device__ float g_bn_a[Cc], g_bn_b[Cc], g_rscale[Cc];
__device__ float g_psum[RCH*Cc], g_psq[RCH*Cc];
// bf16 hi/lo split of BN(x) for qk 3-term GEMM
__device__ __nv_bfloat16 g_Ahi[(size_t)Mm*Cc], g_Alo[(size_t)Mm*Cc];
// fp16 of BN(x) for v 1-term GEMM
__device__ __half g_Ah16[(size_t)Mm*Cc];
// fp16 of (o + dwc) for proj 1-term GEMM
__device__ __half g_Oh16[(size_t)Mm*Cc];
// weights: qk part bf16 hi/lo (transposed, rows = out-cols 0..2047)
__device__ __nv_bfloat16 g_Wqh[(size_t)2048*Cc], g_Wql[(size_t)2048*Cc];
// weights: v part + proj, fp16 (transposed)
__device__ __half g_Wvh[(size_t)Cc*Cc], g_Wph16[(size_t)Cc*Cc];

// ---------------------------------------------------------------------------
// helpers
// ---------------------------------------------------------------------------
__device__ __forceinline__ uint32_t smem_u32(const void* p) {
    uint32_t a;
    asm("{ .reg .u64 t; cvta.to.shared.u64 t, %1; cvt.u32.u64 %0, t; }"
        : "=r"(a) : "l"(p));
    return a;
}
__device__ __forceinline__ void cpa16(uint32_t dst, const void* src) {
    asm volatile("cp.async.cg.shared.global [%0], [%1], 16;" :: "r"(dst), "l"(src));
}
__device__ __forceinline__ void cp_commit() {
    asm volatile("cp.async.commit_group;" ::: "memory");
}
template <int N>
__device__ __forceinline__ void cp_wait() {
    asm volatile("cp.async.wait_group %0;" :: "n"(N) : "memory");
}
__device__ __forceinline__ void ldsm4(uint32_t* r, uint32_t addr) {
    asm volatile("ldmatrix.sync.aligned.m8n8.x4.shared.b16 {%0,%1,%2,%3}, [%4];"
                 : "=r"(r[0]), "=r"(r[1]), "=r"(r[2]), "=r"(r[3]) : "r"(addr));
}
__device__ __forceinline__ void mma_bf(float* d, const uint32_t* a, const uint32_t* b) {
    asm volatile(
        "mma.sync.aligned.m16n8k16.row.col.f32.bf16.bf16.f32 "
        "{%0,%1,%2,%3}, {%4,%5,%6,%7}, {%8,%9}, {%0,%1,%2,%3};"
        : "+f"(d[0]), "+f"(d[1]), "+f"(d[2]), "+f"(d[3])
        : "r"(a[0]), "r"(a[1]), "r"(a[2]), "r"(a[3]), "r"(b[0]), "r"(b[1]));
}
__device__ __forceinline__ void mma_fp(float* d, const uint32_t* a, const uint32_t* b) {
    asm volatile(
        "mma.sync.aligned.m16n8k16.row.col.f32.f16.f16.f32 "
        "{%0,%1,%2,%3}, {%4,%5,%6,%7}, {%8,%9}, {%0,%1,%2,%3};"
        : "+f"(d[0]), "+f"(d[1]), "+f"(d[2]), "+f"(d[3])
        : "r"(a[0]), "r"(a[1]), "r"(a[2]), "r"(a[3]), "r"(b[0]), "r"(b[1]));
}

// ---------------------------------------------------------------------------
// K1: per-channel partial sums (deterministic, no atomics)
// ---------------------------------------------------------------------------
__global__ void bn_partial(const float* __restrict__ x) {
    int c = blockIdx.x * 128 + threadIdx.x;
    int chunk = blockIdx.y;
    const int RPC = Mm / RCH;
    const float* p = x + (size_t)(chunk * RPC) * Cc + c;
    float s = 0.f, sq = 0.f;
    for (int r = 0; r < RPC; r++) { float v = p[(size_t)r * Cc]; s += v; sq += v * v; }
    g_psum[chunk * Cc + c] = s;
    g_psq[chunk * Cc + c]  = sq;
}

// ---------------------------------------------------------------------------
// K2: finalize BN affine + reciprocal softplus(scale_p)
// ---------------------------------------------------------------------------
__global__ void bn_finalize(const float* __restrict__ gamma,
                            const float* __restrict__ beta,
                            const float* __restrict__ scale_p) {
    int c = blockIdx.x * 256 + threadIdx.x;
    float s = 0.f, sq = 0.f;
    for (int i = 0; i < RCH; i++) { s += g_psum[i * Cc + c]; sq += g_psq[i * Cc + c]; }
    float mean = s / (float)Mm;
    float var  = sq / (float)Mm - mean * mean;
    float rstd = rsqrtf(var + 1e-5f);
    float a = rstd * gamma[c];
    g_bn_a[c] = a;
    g_bn_b[c] = beta[c] - mean * a;
    float sp = scale_p[c];
    float sc = (sp > 20.f) ? sp : log1pf(expf(sp));
    g_rscale[c] = 1.0f / sc;
}

// ---------------------------------------------------------------------------
// K3: xn = BN(x) -> bf16 hi/lo AND fp16 hi
// ---------------------------------------------------------------------------
__global__ void prep_x(const float* __restrict__ x) {
    size_t i = (size_t)blockIdx.x * 256 + threadIdx.x;   // float4 index
    float4 v = ((const float4*)x)[i];
    int c = (int)((i * 4) & (Cc - 1));
    float f[4];
    f[0] = v.x * g_bn_a[c]     + g_bn_b[c];
    f[1] = v.y * g_bn_a[c + 1] + g_bn_b[c + 1];
    f[2] = v.z * g_bn_a[c + 2] + g_bn_b[c + 2];
    f[3] = v.w * g_bn_a[c + 3] + g_bn_b[c + 3];

    __nv_bfloat162* ph = (__nv_bfloat162*)g_Ahi;
    __nv_bfloat162* pl = (__nv_bfloat162*)g_Alo;
    __nv_bfloat16 bh[4], bl[4];
#pragma unroll
    for (int j = 0; j < 4; j++) {
        bh[j] = __float2bfloat16(f[j]);
        bl[j] = __float2bfloat16(f[j] - __bfloat162float(bh[j]));
    }
    ph[i * 2]     = {bh[0], bh[1]};
    ph[i * 2 + 1] = {bh[2], bh[3]};
    pl[i * 2]     = {bl[0], bl[1]};
    pl[i * 2 + 1] = {bl[2], bl[3]};

    __half2* qh = (__half2*)g_Ah16;
    qh[i * 2]     = {__float2half(f[0]), __float2half(f[1])};
    qh[i * 2 + 1] = {__float2half(f[2]), __float2half(f[3])};
}

// ---------------------------------------------------------------------------
// K4a: transpose W [K=1024, Nout] cols [0,2048) -> bf16 hi/lo rows
// ---------------------------------------------------------------------------
__global__ void prep_w_bf(const float* __restrict__ W,
                          __nv_bfloat16* __restrict__ hi, __nv_bfloat16* __restrict__ lo,
                          int Nout) {
    __shared__ float tile[32][33];
    int n0 = blockIdx.x * 32, k0 = blockIdx.y * 32;
    int tx = threadIdx.x, ty = threadIdx.y;     // (32, 8)
#pragma unroll
    for (int j = 0; j < 32; j += 8)
        tile[ty + j][tx] = W[(size_t)(k0 + ty + j) * Nout + n0 + tx];
    __syncthreads();
#pragma unroll
    for (int j = 0; j < 32; j += 8) {
        float v = tile[tx][ty + j];
        size_t oi = (size_t)(n0 + ty + j) * Cc + k0 + tx;
        __nv_bfloat16 h = __float2bfloat16(v);
        hi[oi] = h;
        lo[oi] = __float2bfloat16(v - __bfloat162float(h));
    }
}

// ---------------------------------------------------------------------------
// K4b: transpose W [K=1024, Nout] cols [nbase, nbase+1024) -> fp16 rows
// ---------------------------------------------------------------------------
__global__ void prep_w_fp(const float* __restrict__ W,
                          __half* __restrict__ hi, int Nout, int nbase) {
    __shared__ float tile[32][33];
    int n0 = nbase + blockIdx.x * 32, k0 = blockIdx.y * 32;
    int tx = threadIdx.x, ty = threadIdx.y;     // (32, 8)
#pragma unroll
    for (int j = 0; j < 32; j += 8)
        tile[ty + j][tx] = W[(size_t)(k0 + ty + j) * Nout + n0 + tx];
    __syncthreads();
#pragma unroll
    for (int j = 0; j < 32; j += 8) {
        float v = tile[tx][ty + j];
        size_t oi = (size_t)(n0 - nbase + ty + j) * Cc + k0 + tx;
        hi[oi] = __float2half(v);
    }
}

// ---------------------------------------------------------------------------
// K5: bf16 3-term HMMA GEMM (AhiBhi + AhiBlo + AloBhi)
// BM=128, BN=256, BK=32. 8 warps (2x4), warp tile 64x64. 3-stage cp.async.
// ---------------------------------------------------------------------------
#define SROW 80
#define T_AH 0
#define T_AL 10240
#define T_BH 20480
#define T_BL 40960
#define STG3 61440
#define NST3 3

__global__ __launch_bounds__(256, 1)
void gemm3_bf(const __nv_bfloat16* __restrict__ Ahi, const __nv_bfloat16* __restrict__ Alo,
              const __nv_bfloat16* __restrict__ Bhi, const __nv_bfloat16* __restrict__ Blo,
              const float* __restrict__ bias, float* __restrict__ Cout, int Ndim) {
    extern __shared__ char sm[];
    const int t = threadIdx.x;
    const int wid = t >> 5, lane = t & 31;
    const int m0 = blockIdx.y * 128, n0 = blockIdx.x * 256;
    const int warp_m = wid & 1, warp_n = wid >> 1;   // 2 x 4 warp grid
    const uint32_t sb = smem_u32(sm);

    float acc[4][8][4];
#pragma unroll
    for (int i = 0; i < 4; i++)
#pragma unroll
        for (int j = 0; j < 8; j++)
#pragma unroll
            for (int q = 0; q < 4; q++) acc[i][j][q] = 0.f;

    const int ar0 = t >> 2, ac = t & 3;
    const int ar1 = ar0 + 64;
    uint32_t da0 = (uint32_t)ar0 * SROW + ac * 16;
    uint32_t da1 = (uint32_t)ar1 * SROW + ac * 16;

#define LOAD3(IT)                                                                   \
    {                                                                               \
        int k0_ = (IT) * 32;                                                        \
        uint32_t dst = sb + ((IT) % NST3) * STG3;                                   \
        cpa16(dst + T_AH + da0, Ahi + (size_t)(m0 + ar0) * Cc + k0_ + ac * 8);      \
        cpa16(dst + T_AH + da1, Ahi + (size_t)(m0 + ar1) * Cc + k0_ + ac * 8);      \
        cpa16(dst + T_AL + da0, Alo + (size_t)(m0 + ar0) * Cc + k0_ + ac * 8);      \
        cpa16(dst + T_AL + da1, Alo + (size_t)(m0 + ar1) * Cc + k0_ + ac * 8);      \
        _Pragma("unroll")                                                           \
        for (int j = 0; j < 4; j++) {                                               \
            int br = ar0 + j * 64;                                                  \
            uint32_t db = (uint32_t)br * SROW + ac * 16;                            \
            cpa16(dst + T_BH + db, Bhi + (size_t)(n0 + br) * Cc + k0_ + ac * 8);    \
            cpa16(dst + T_BL + db, Blo + (size_t)(n0 + br) * Cc + k0_ + ac * 8);    \
        }                                                                           \
        cp_commit();                                                                \
    }

    LOAD3(0)
    LOAD3(1)

    const uint32_t a_off = (uint32_t)(warp_m * 64 + (lane & 15)) * SROW + ((lane >> 4) << 3) * 2;
    const uint32_t b_off = (uint32_t)(warp_n * 64 + ((lane & 16) >> 1) + (lane & 7)) * SROW + (lane & 8) * 2;

    for (int it = 0; it < 32; it++) {
        if (it < 31) cp_wait<1>(); else cp_wait<0>();
        __syncthreads();
        if (it + 2 < 32) LOAD3(it + 2)

        uint32_t base = sb + (it % NST3) * STG3;
#pragma unroll
        for (int kk2 = 0; kk2 < 2; kk2++) {
            uint32_t ko = kk2 * 32;
            uint32_t ah[4][4], al[4][4];
#pragma unroll
            for (int mt = 0; mt < 4; mt++) {
                ldsm4(ah[mt], base + T_AH + a_off + mt * 16 * SROW + ko);
                ldsm4(al[mt], base + T_AL + a_off + mt * 16 * SROW + ko);
            }
#pragma unroll
            for (int nt2 = 0; nt2 < 4; nt2++) {
                uint32_t bhf[4], blf[4];
                ldsm4(bhf, base + T_BH + b_off + nt2 * 16 * SROW + ko);
                ldsm4(blf, base + T_BL + b_off + nt2 * 16 * SROW + ko);
#pragma unroll
                for (int mt = 0; mt < 4; mt++)
#pragma unroll
                    for (int hf = 0; hf < 2; hf++) {
                        int nt = nt2 * 2 + hf;
                        mma_bf(acc[mt][nt], ah[mt], &bhf[hf * 2]);
                        mma_bf(acc[mt][nt], ah[mt], &blf[hf * 2]);
                        mma_bf(acc[mt][nt], al[mt], &bhf[hf * 2]);
                    }
            }
        }
    }

#pragma unroll
    for (int mt = 0; mt < 4; mt++) {
        int row = m0 + warp_m * 64 + mt * 16 + (lane >> 2);
#pragma unroll
        for (int nt = 0; nt < 8; nt++) {
            int col = n0 + warp_n * 64 + nt * 8 + (lane & 3) * 2;
            float b0 = bias[col], b1 = bias[col + 1];
            float2* p0 = (float2*)(Cout + (size_t)row * Ndim + col);
            float2* p1 = (float2*)(Cout + (size_t)(row + 8) * Ndim + col);
            *p0 = {acc[mt][nt][0] + b0, acc[mt][nt][1] + b1};
            *p1 = {acc[mt][nt][2] + b0, acc[mt][nt][3] + b1};
        }
    }
}

// ---------------------------------------------------------------------------
// K5b: fp16 single-term HMMA GEMM (A @ B^T), both fp16
// Same tiling; stage = A(10240) | B(20480) = 30720 B, 3 stages.
// ---------------------------------------------------------------------------
#define T1_A 0
#define T1_B 10240
#define STG1 30720
#define NST1 3

__global__ __launch_bounds__(256, 1)
void gemm1_fp(const __half* __restrict__ A, const __half* __restrict__ Bm,
              const float* __restrict__ bias, float* __restrict__ Cout, int Ndim) {
    extern __shared__ char sm[];
    const int t = threadIdx.x;
    const int wid = t >> 5, lane = t & 31;
    const int m0 = blockIdx.y * 128, n0 = blockIdx.x * 256;
    const int warp_m = wid & 1, warp_n = wid >> 1;
    const uint32_t sb = smem_u32(sm);

    float acc[4][8][4];
#pragma unroll
    for (int i = 0; i < 4; i++)
#pragma unroll
        for (int j = 0; j < 8; j++)
#pragma unroll
            for (int q = 0; q < 4; q++) acc[i][j][q] = 0.f;

    const int ar0 = t >> 2, ac = t & 3;
    const int ar1 = ar0 + 64;
    uint32_t da0 = (uint32_t)ar0 * SROW + ac * 16;
    uint32_t da1 = (uint32_t)ar1 * SROW + ac * 16;

#define LOAD1(IT)                                                                   \
    {                                                                               \
        int k0_ = (IT) * 32;                                                        \
        uint32_t dst = sb + ((IT) % NST1) * STG1;                                   \
        cpa16(dst + T1_A + da0, A + (size_t)(m0 + ar0) * Cc + k0_ + ac * 8);        \
        cpa16(dst + T1_A + da1, A + (size_t)(m0 + ar1) * Cc + k0_ + ac * 8);        \
        _Pragma("unroll")                                                           \
        for (int j = 0; j < 4; j++) {                                               \
            int br = ar0 + j * 64;                                                  \
            uint32_t db = (uint32_t)br * SROW + ac * 16;                            \
            cpa16(dst + T1_B + db, Bm + (size_t)(n0 + br) * Cc + k0_ + ac * 8);     \
        }                                                                           \
        cp_commit();                                                                \
    }

    LOAD1(0)
    LOAD1(1)

    const uint32_t a_off = (uint32_t)(warp_m * 64 + (lane & 15)) * SROW + ((lane >> 4) << 3) * 2;
    const uint32_t b_off = (uint32_t)(warp_n * 64 + ((lane & 16) >> 1) + (lane & 7)) * SROW + (lane & 8) * 2;

    for (int it = 0; it < 32; it++) {
        if (it < 31) cp_wait<1>(); else cp_wait<0>();
        __syncthreads();
        if (it + 2 < 32) LOAD1(it + 2)

        uint32_t base = sb + (it % NST1) * STG1;
#pragma unroll
        for (int kk2 = 0; kk2 < 2; kk2++) {
            uint32_t ko = kk2 * 32;
            uint32_t ah[4][4];
#pragma unroll
            for (int mt = 0; mt < 4; mt++)
                ldsm4(ah[mt], base + T1_A + a_off + mt * 16 * SROW + ko);
#pragma unroll
            for (int nt2 = 0; nt2 < 4; nt2++) {
                uint32_t bhf[4];
                ldsm4(bhf, base + T1_B + b_off + nt2 * 16 * SROW + ko);
#pragma unroll
                for (int mt = 0; mt < 4; mt++)
#pragma unroll
                    for (int hf = 0; hf < 2; hf++)
                        mma_fp(acc[mt][nt2 * 2 + hf], ah[mt], &bhf[hf * 2]);
            }
        }
    }

#pragma unroll
    for (int mt = 0; mt < 4; mt++) {
        int row = m0 + warp_m * 64 + mt * 16 + (lane >> 2);
#pragma unroll
        for (int nt = 0; nt < 8; nt++) {
            int col = n0 + warp_n * 64 + nt * 8 + (lane & 3) * 2;
            float b0 = bias[col], b1 = bias[col + 1];
            float2* p0 = (float2*)(Cout + (size_t)row * Ndim + col);
            float2* p1 = (float2*)(Cout + (size_t)(row + 8) * Ndim + col);
            *p0 = {acc[mt][nt][0] + b0, acc[mt][nt][1] + b1};
            *p1 = {acc[mt][nt][2] + b0, acc[mt][nt][3] + b1};
        }
    }
}

// ---------------------------------------------------------------------------
// K6: focused feature map, in place on q / k rows
// ---------------------------------------------------------------------------
__global__ void focus_kernel() {
    int bx  = blockIdx.x;
    int m   = bx >> 1;
    int sel = bx & 1;
    float* p = g_qkv + (size_t)m * C3 + sel * Cc;
    int t = threadIdx.x;

    float t3[4];
    float s2 = 0.f, s6 = 0.f;
#pragma unroll
    for (int i = 0; i < 4; i++) {
        int c = t + i * 256;
        float v = fmaxf(p[c], 0.f) + 1e-6f;
        v = v * g_rscale[c];
        s2 += v * v;
        float v3 = v * v * v;
        t3[i] = v3;
        s6 += v3 * v3;
    }
    __shared__ float sh2[8], sh6[8];
#pragma unroll
    for (int off = 16; off; off >>= 1) {
        s2 += __shfl_xor_sync(0xffffffffu, s2, off);
        s6 += __shfl_xor_sync(0xffffffffu, s6, off);
    }
    int w = t >> 5, lane = t & 31;
    if (lane == 0) { sh2[w] = s2; sh6[w] = s6; }
    __syncthreads();
    if (t == 0) {
        float a = 0.f, b = 0.f;
        for (int i = 0; i < 8; i++) { a += sh2[i]; b += sh6[i]; }
        sh2[0] = a; sh6[0] = b;
    }
    __syncthreads();
    float factor = sqrtf(sh2[0] / sh6[0]);
#pragma unroll
    for (int i = 0; i < 4; i++) p[t + i * 256] = t3[i] * factor;
}

// ---------------------------------------------------------------------------
// K7: per (b,h): kv[d][e] = sum_n k[n,d] v[n,e]; ksum[d] = sum_n k[n,d]
// ---------------------------------------------------------------------------
__global__ __launch_bounds__(256) void kv_kernel() {
    int bh = blockIdx.x;
    int b = bh >> 4, h = bh & 15;
    const float* kbase = g_qkv + (size_t)(b * Nn) * C3 + Cc + h * Dd;
    const float* vbase = kbase + Cc;

    __shared__ float ks[32][65], vs[32][65];
    int t = threadIdx.x;
    int dr = (t >> 4) << 2, ec = (t & 15) << 2;

    float acc[4][4];
#pragma unroll
    for (int i = 0; i < 4; i++)
#pragma unroll
        for (int j = 0; j < 4; j++) acc[i][j] = 0.f;
    float ksacc = 0.f;

    for (int n0 = 0; n0 < Nn; n0 += 32) {
        __syncthreads();
#pragma unroll
        for (int i = 0; i < 8; i++) {
            int idx = t + i * 256;
            int r = idx >> 6, c = idx & 63;
            ks[r][c] = kbase[(size_t)(n0 + r) * C3 + c];
            vs[r][c] = vbase[(size_t)(n0 + r) * C3 + c];
        }
        __syncthreads();
#pragma unroll 8
        for (int n = 0; n < 32; n++) {
            float kd0 = ks[n][dr], kd1 = ks[n][dr + 1], kd2 = ks[n][dr + 2], kd3 = ks[n][dr + 3];
            float v0 = vs[n][ec], v1 = vs[n][ec + 1], v2 = vs[n][ec + 2], v3 = vs[n][ec + 3];
            acc[0][0] += kd0 * v0; acc[0][1] += kd0 * v1; acc[0][2] += kd0 * v2; acc[0][3] += kd0 * v3;
            acc[1][0] += kd1 * v0; acc[1][1] += kd1 * v1; acc[1][2] += kd1 * v2; acc[1][3] += kd1 * v3;
            acc[2][0] += kd2 * v0; acc[2][1] += kd2 * v1; acc[2][2] += kd2 * v2; acc[2][3] += kd2 * v3;
            acc[3][0] += kd3 * v0; acc[3][1] += kd3 * v1; acc[3][2] += kd3 * v2; acc[3][3] += kd3 * v3;
        }
        if (t < 64) {
#pragma unroll 8
            for (int n = 0; n < 32; n++) ksacc += ks[n][t];
        }
    }

    float* kvout = g_kv + bh * (Dd * Dd);
#pragma unroll
    for (int i = 0; i < 4; i++)
#pragma unroll
        for (int j = 0; j < 4; j++)
            kvout[(dr + i) * Dd + ec + j] = acc[i][j];
    if (t < 64) g_ksum[bh * Dd + t] = ksacc;
}

// ---------------------------------------------------------------------------
// K8: o = (q @ kv) * z fused with depthwise conv; writes fp16 for proj
// ---------------------------------------------------------------------------
__global__ __launch_bounds__(256) void o_dwc_kernel(const float* __restrict__ dwc_w,
                                                    const float* __restrict__ dwc_b) {
    int bh = blockIdx.x;
    int b = bh >> 4, h = bh & 15;
    int n0 = blockIdx.y * 128;

    __shared__ float kvs[64][65];
    __shared__ float ksums[64];
    __shared__ float qrow[8][64];

    int t = threadIdx.x;
    int w = t >> 5, lane = t & 31;

#pragma unroll
    for (int i = 0; i < 16; i++) {
        int idx = t + i * 256;
        kvs[idx >> 6][idx & 63] = g_kv[bh * (Dd * Dd) + idx];
    }
    if (t < 64) ksums[t] = g_ksum[bh * Dd + t];
    __syncthreads();

    const float* qbase = g_qkv + (size_t)(b * Nn) * C3 + h * Dd;
    const float* vbase = g_qkv + (size_t)(b * Nn) * C3 + 2 * Cc + h * Dd;

    int c0 = h * 64 + lane, c1 = h * 64 + lane + 32;
    float w0[5], w1[5];
#pragma unroll
    for (int j = 0; j < 5; j++) { w0[j] = dwc_w[c0 * 5 + j]; w1[j] = dwc_w[c1 * 5 + j]; }
    float db0 = dwc_b[c0], db1 = dwc_b[c1];

    for (int r = w; r < 128; r += 8) {
        int n = n0 + r;
        const float* qp = qbase + (size_t)n * C3;
        qrow[w][lane]      = qp[lane];
        qrow[w][lane + 32] = qp[lane + 32];
        __syncwarp();

        float s = qrow[w][lane] * ksums[lane] + qrow[w][lane + 32] * ksums[lane + 32];
#pragma unroll
        for (int off = 16; off; off >>= 1) s += __shfl_xor_sync(0xffffffffu, s, off);
        float z = 1.f / (s + 1e-6f);

        float acc0 = 0.f, acc1 = 0.f;
#pragma unroll
        for (int d = 0; d < 64; d++) {
            float qd = qrow[w][d];
            acc0 += qd * kvs[d][lane];
            acc1 += qd * kvs[d][lane + 32];
        }

        float dw0 = db0, dw1 = db1;
#pragma unroll
        for (int j = 0; j < 5; j++) {
            int nn = n + j - 2;
            if ((unsigned)nn < (unsigned)Nn) {
                const float* vp = vbase + (size_t)nn * C3;
                dw0 += vp[lane]      * w0[j];
                dw1 += vp[lane + 32] * w1[j];
            }
        }

        float o0 = acc0 * z + dw0;
        float o1 = acc1 * z + dw1;
        size_t oi = (size_t)(b * Nn + n) * Cc + h * 64;
        g_Oh16[oi + lane]      = __float2half(o0);
        g_Oh16[oi + lane + 32] = __float2half(o1);
        __syncwarp();
    }
}

// ---------------------------------------------------------------------------
extern "C" void kernel_launch(void* const* d_in, const int* in_sizes, int n_in,
                              void* d_out, int out_size) {
    const float* x       = (const float*)d_in[0];
    const float* gamma   = (const float*)d_in[1];
    const float* beta    = (const float*)d_in[2];
    const float* Wqkv    = (const float*)d_in[3];
    const float* bqkv    = (const float*)d_in[4];
    const float* scale_p = (const float*)d_in[5];
    const float* dwc_w   = (const float*)d_in[6];
    const float* dwc_b   = (const float*)d_in[7];
    const float* Wproj   = (const float*)d_in[8];
    const float* bproj   = (const float*)d_in[9];
    float* out = (float*)d_out;

    void *p_qkv, *p_Ahi, *p_Alo, *p_Ah16, *p_Oh16;
    void *p_Wqh, *p_Wql, *p_Wvh, *p_Wph16;
    cudaGetSymbolAddress(&p_qkv, g_qkv);
    cudaGetSymbolAddress(&p_Ahi, g_Ahi);
    cudaGetSymbolAddress(&p_Alo, g_Alo);
    cudaGetSymbolAddress(&p_Ah16, g_Ah16);
    cudaGetSymbolAddress(&p_Oh16, g_Oh16);
    cudaGetSymbolAddress(&p_Wqh, g_Wqh);
    cudaGetSymbolAddress(&p_Wql, g_Wql);
    cudaGetSymbolAddress(&p_Wvh, g_Wvh);
    cudaGetSymbolAddress(&p_Wph16, g_Wph16);

    static int attr_done = 0;
    if (!attr_done) {
        cudaFuncSetAttribute(gemm3_bf, cudaFuncAttributeMaxDynamicSharedMemorySize, NST3 * STG3);
        cudaFuncSetAttribute(gemm1_fp, cudaFuncAttributeMaxDynamicSharedMemorySize, NST1 * STG1);
        attr_done = 1;
    }

    // 1. BN stats
    bn_partial<<<dim3(8, RCH), 128>>>(x);
    bn_finalize<<<4, 256>>>(gamma, beta, scale_p);

    // 2. operand prep
    prep_x<<<(Mm * Cc / 4) / 256, 256>>>(x);
    prep_w_bf<<<dim3(64, 32), dim3(32, 8)>>>(Wqkv, (__nv_bfloat16*)p_Wqh, (__nv_bfloat16*)p_Wql, C3);
    prep_w_fp<<<dim3(32, 32), dim3(32, 8)>>>(Wqkv, (__half*)p_Wvh, C3, 2048);
    prep_w_fp<<<dim3(32, 32), dim3(32, 8)>>>(Wproj, (__half*)p_Wph16, Cc, 0);

    // 3a. qk GEMM (bf16 3-term): [16384,1024]@[1024,2048]
    gemm3_bf<<<dim3(2048 / 256, Mm / 128), 256, NST3 * STG3>>>(
        (const __nv_bfloat16*)p_Ahi, (const __nv_bfloat16*)p_Alo,
        (const __nv_bfloat16*)p_Wqh, (const __nv_bfloat16*)p_Wql,
        bqkv, (float*)p_qkv, C3);

    // 3b. v GEMM (fp16 1-term): [16384,1024]@[1024,1024] -> qkv cols [2048,3072)
    gemm1_fp<<<dim3(Cc / 256, Mm / 128), 256, NST1 * STG1>>>(
        (const __half*)p_Ah16, (const __half*)p_Wvh,
        bqkv + 2048, (float*)p_qkv + 2048, C3);

    // 4. focus(q), focus(k) in place
    focus_kernel<<<2 * Mm, 256>>>();

    // 5. per-(b,h) K^T V and k-sum
    kv_kernel<<<Bb * Hh, 256>>>();

    // 6. o = (q @ kv) * z + dwc residual -> fp16
    o_dwc_kernel<<<dim3(Bb * Hh, Nn / 128), 256>>>(dwc_w, dwc_b);

    // 7. proj GEMM (fp16 1-term): [16384,1024]@[1024,1024] + bias -> out
    gemm1_fp<<<dim3(Cc / 256, Mm / 128), 256, NST1 * STG1>>>(
        (const __half*)p_Oh16, (const __half*)p_Wph16,
        bproj, out, Cc);
}